// round 2
// baseline (speedup 1.0000x reference)
#include <cuda_runtime.h>

// CTNNBackflowStyleJastrow: B=1024, N=32, D=3, H=M=32, RH=64
// One CTA (256 threads = 8 warps) per batch element.
// Edge loop: warp-cooperative, lane = hidden channel. No per-thread arrays.

__device__ __forceinline__ float silu_f(float x) {
    return x / (1.0f + __expf(-x));
}

__global__ __launch_bounds__(256, 1)
void jastrow_kernel(const float* __restrict__ x,
                    const float* __restrict__ W_node, const float* __restrict__ b_node,
                    const float* __restrict__ We1,  const float* __restrict__ be1,
                    const float* __restrict__ We2,  const float* __restrict__ be2,
                    const float* __restrict__ Wv2e, const float* __restrict__ We2v,
                    const float* __restrict__ Wu1,  const float* __restrict__ bu1,
                    const float* __restrict__ Wu2,  const float* __restrict__ bu2,
                    const float* __restrict__ Wn1,  const float* __restrict__ bn1,
                    const float* __restrict__ Wn2,  const float* __restrict__ bn2,
                    const float* __restrict__ Wf1,  const float* __restrict__ bf1,
                    const float* __restrict__ Wf2,  const float* __restrict__ bf2,
                    const float* __restrict__ Wf3,  const float* __restrict__ bf3,
                    float* __restrict__ out)
{
    // Transposed weight stages: [k*33 + row] = W[row][k]  (conflict-free lane fills)
    __shared__ float sWe2T[32 * 33];
    __shared__ float sWu1T[32 * 33];   // Wu1[:, 0:32] part only
    __shared__ float sWu2T[32 * 33];

    __shared__ float sx[96];           // x for this batch (OMEGA = 1 so x_sc == x)
    __shared__ float shv[32 * 33];     // h_v (pre-update), [i*33 + h]
    __shared__ float sp [32 * 33];     // p, later m_v
    __shared__ float sq [32 * 33];     // q_i = Wu1[:,32:64]@p_i + bu1, later a1
    __shared__ float ssj[32 * 33];     // s_j = Wu1[:,64:96]@p_j, later h_v_new
    __shared__ float srs[32 * 33];     // row sums of h_e_new
    __shared__ float spair[32];        // sum over i<j of (h_e + h_e_new)
    __shared__ float sred[3];          // r2_sum, s1_sum, cusp_sum
    __shared__ float sfin[132], sf1[64], sf2[64];
    __shared__ __align__(16) float sbuf[8 * 64];   // per-warp staging: [w*64 .. w*64+31]=A, +32..63=B

    const int tid  = threadIdx.x;
    const int lane = tid & 31;
    const int w    = tid >> 5;
    const int b    = blockIdx.x;

    // ---- stage inputs & transposed weights ----
    if (tid < 96) sx[tid] = x[b * 96 + tid];
    if (tid < 32) spair[tid] = 0.0f;
    if (tid < 3)  sred[tid] = 0.0f;
    for (int idx = tid; idx < 1024; idx += 256) {
        int r = idx >> 5, k = idx & 31;          // r = weight row, k = column
        sWe2T[k * 33 + r] = We2[r * 32 + k];
        sWu1T[k * 33 + r] = Wu1[r * 96 + k];
        sWu2T[k * 33 + r] = Wu2[r * 32 + k];
    }
    __syncthreads();

    // ---- node phases: lane = node index i, (warp,iter) = channel ----
    // h_v = [x, spin] @ W_node^T + b_node
    #pragma unroll
    for (int it = 0; it < 4; it++) {
        int ch = w + it * 8;                     // channel h
        int i  = lane;
        float sf = (i >= 16) ? 1.0f : 0.0f;
        float a = b_node[ch]
                + W_node[ch * 4 + 0] * sx[i * 3 + 0]
                + W_node[ch * 4 + 1] * sx[i * 3 + 1]
                + W_node[ch * 4 + 2] * sx[i * 3 + 2]
                + W_node[ch * 4 + 3] * sf;
        shv[i * 33 + ch] = a;
    }
    __syncthreads();

    // p = h_v @ Wv2e^T   (channel = m)
    #pragma unroll
    for (int it = 0; it < 4; it++) {
        int m = w + it * 8;
        int i = lane;
        float a0 = 0.f, a1 = 0.f, a2 = 0.f, a3 = 0.f;
        #pragma unroll
        for (int h = 0; h < 32; h += 4) {
            a0 = fmaf(Wv2e[m * 32 + h + 0], shv[i * 33 + h + 0], a0);
            a1 = fmaf(Wv2e[m * 32 + h + 1], shv[i * 33 + h + 1], a1);
            a2 = fmaf(Wv2e[m * 32 + h + 2], shv[i * 33 + h + 2], a2);
            a3 = fmaf(Wv2e[m * 32 + h + 3], shv[i * 33 + h + 3], a3);
        }
        sp[i * 33 + m] = (a0 + a1) + (a2 + a3);
    }
    __syncthreads();

    // q_i = Wu1[:,32:64]@p_i + bu1 ; s_j = Wu1[:,64:96]@p_j   (channel = h)
    #pragma unroll
    for (int it = 0; it < 4; it++) {
        int h = w + it * 8;
        int i = lane;
        float aq = bu1[h], as = 0.f;
        #pragma unroll
        for (int m = 0; m < 32; m++) {
            float pv = sp[i * 33 + m];
            aq = fmaf(Wu1[h * 96 + 32 + m], pv, aq);
            as = fmaf(Wu1[h * 96 + 64 + m], pv, as);
        }
        sq [i * 33 + h] = aq;
        ssj[i * 33 + h] = as;
    }
    __syncthreads();

    // ---- fill per-lane weight rows (row = lane) ----
    float We1r0 = We1[lane * 5 + 0], We1r1 = We1[lane * 5 + 1], We1r2 = We1[lane * 5 + 2];
    float We1r3 = We1[lane * 5 + 3], We1r4 = We1[lane * 5 + 4];
    float be1r = be1[lane], be2r = be2[lane], bu2r = bu2[lane];
    float We2r[32], Wu1r[32], Wu2r[32];
    #pragma unroll
    for (int k = 0; k < 32; k++) {
        We2r[k] = sWe2T[k * 33 + lane];
        Wu1r[k] = sWu1T[k * 33 + lane];
        Wu2r[k] = sWu2T[k * 33 + lane];
    }

    float*  bufA  = &sbuf[w * 64];
    float*  bufB  = &sbuf[w * 64 + 32];
    const float4* A4 = reinterpret_cast<const float4*>(bufA);
    const float4* B4 = reinterpret_cast<const float4*>(bufB);

    float pacc = 0.0f;

    // ---- edge loop: warp w owns rows i = 4w..4w+3, lane = channel ----
    #pragma unroll 1
    for (int ii = 0; ii < 4; ii++) {
        const int i = w * 4 + ii;
        const float xi0 = sx[i * 3 + 0], xi1 = sx[i * 3 + 1], xi2 = sx[i * 3 + 2];
        const float qv  = sq[i * 33 + lane];
        float racc = 0.0f;

        #pragma unroll 1
        for (int j = 0; j < 32; j++) {
            float r0 = xi0 - sx[j * 3 + 0];
            float r1 = xi1 - sx[j * 3 + 1];
            float r2 = xi2 - sx[j * 3 + 2];
            float rr2 = fmaf(r0, r0, fmaf(r1, r1, r2 * r2));
            float rr1 = sqrtf(rr2 + 1e-12f);

            // layer e1 (lane h): t = silu(We1_h . [r, r1, r2] + be1_h)
            float tt = be1r;
            tt = fmaf(We1r0, r0, tt);  tt = fmaf(We1r1, r1, tt);
            tt = fmaf(We1r2, r2, tt);  tt = fmaf(We1r3, rr1, tt);
            tt = fmaf(We1r4, rr2, tt);
            tt = silu_f(tt);

            __syncwarp();              // prior iter's readers of bufA done
            bufA[lane] = tt;
            __syncwarp();

            // h_e (lane c) = be2_c + We2_c . t
            float a0 = be2r, a1 = 0.f, a2 = 0.f, a3 = 0.f;
            #pragma unroll
            for (int k = 0; k < 8; k++) {
                float4 tv = A4[k];
                a0 = fmaf(We2r[4 * k + 0], tv.x, a0);
                a1 = fmaf(We2r[4 * k + 1], tv.y, a1);
                a2 = fmaf(We2r[4 * k + 2], tv.z, a2);
                a3 = fmaf(We2r[4 * k + 3], tv.w, a3);
            }
            float he = (a0 + a1) + (a2 + a3);
            bufB[lane] = he;
            __syncwarp();

            // t2 (lane h) = silu(q_i + s_j + Wu1a_h . h_e)
            float u0 = qv + ssj[j * 33 + lane], u1 = 0.f, u2 = 0.f, u3 = 0.f;
            #pragma unroll
            for (int k = 0; k < 8; k++) {
                float4 hv = B4[k];
                u0 = fmaf(Wu1r[4 * k + 0], hv.x, u0);
                u1 = fmaf(Wu1r[4 * k + 1], hv.y, u1);
                u2 = fmaf(Wu1r[4 * k + 2], hv.z, u2);
                u3 = fmaf(Wu1r[4 * k + 3], hv.w, u3);
            }
            float t2 = silu_f((u0 + u1) + (u2 + u3));
            bufA[lane] = t2;           // t already fully consumed (pre-he sync)
            __syncwarp();

            // h_e_new (lane c) = bu2_c + Wu2_c . t2
            float h0 = bu2r, h1 = 0.f, h2 = 0.f, h3 = 0.f;
            #pragma unroll
            for (int k = 0; k < 8; k++) {
                float4 tv = A4[k];
                h0 = fmaf(Wu2r[4 * k + 0], tv.x, h0);
                h1 = fmaf(Wu2r[4 * k + 1], tv.y, h1);
                h2 = fmaf(Wu2r[4 * k + 2], tv.z, h2);
                h3 = fmaf(Wu2r[4 * k + 3], tv.w, h3);
            }
            float hn = (h0 + h1) + (h2 + h3);

            if (i != j) racc += hn;
            if (i < j)  pacc += he + hn;
        }
        srs[i * 33 + lane] = racc;     // warp-exclusive row: no atomics
    }
    atomicAdd(&spair[lane], pacc);
    __syncthreads();

    // ---- m_v = We2v @ rowsum  (reuse sp; channel = h) ----
    #pragma unroll
    for (int it = 0; it < 4; it++) {
        int h = w + it * 8;
        int i = lane;
        float a0 = 0.f, a1 = 0.f, a2 = 0.f, a3 = 0.f;
        #pragma unroll
        for (int c = 0; c < 32; c += 4) {
            a0 = fmaf(We2v[h * 32 + c + 0], srs[i * 33 + c + 0], a0);
            a1 = fmaf(We2v[h * 32 + c + 1], srs[i * 33 + c + 1], a1);
            a2 = fmaf(We2v[h * 32 + c + 2], srs[i * 33 + c + 2], a2);
            a3 = fmaf(We2v[h * 32 + c + 3], srs[i * 33 + c + 3], a3);
        }
        sp[i * 33 + h] = (a0 + a1) + (a2 + a3);
    }
    __syncthreads();

    // ---- a1 = silu(Wn1 @ [h_v, m_v] + bn1)  (reuse sq) ----
    #pragma unroll
    for (int it = 0; it < 4; it++) {
        int h = w + it * 8;
        int i = lane;
        float a = bn1[h];
        #pragma unroll
        for (int k = 0; k < 32; k++) a = fmaf(Wn1[h * 64 + k],      shv[i * 33 + k], a);
        #pragma unroll
        for (int k = 0; k < 32; k++) a = fmaf(Wn1[h * 64 + 32 + k], sp [i * 33 + k], a);
        sq[i * 33 + h] = silu_f(a);
    }
    __syncthreads();

    // ---- h_v_new = h_v + Wn2 @ a1 + bn2  (reuse ssj) ----
    #pragma unroll
    for (int it = 0; it < 4; it++) {
        int h = w + it * 8;
        int i = lane;
        float a = shv[i * 33 + h] + bn2[h];
        #pragma unroll
        for (int c = 0; c < 32; c++) a = fmaf(Wn2[h * 32 + c], sq[i * 33 + c], a);
        ssj[i * 33 + h] = a;
    }

    // ---- pairwise scalars: r2_sum, s1_sum, cusp ----
    float r2_l = 0.0f, s1_l = 0.0f, cusp_l = 0.0f;
    if (tid < 96) r2_l = sx[tid] * sx[tid];
    for (int idx = tid; idx < 496; idx += 256) {
        int rem = idx, pi = 0, cnt = 31;
        while (rem >= cnt) { rem -= cnt; pi++; cnt--; }
        int pj = pi + 1 + rem;
        float d0 = sx[pi * 3 + 0] - sx[pj * 3 + 0];
        float d1 = sx[pi * 3 + 1] - sx[pj * 3 + 1];
        float d2 = sx[pi * 3 + 2] - sx[pj * 3 + 2];
        float dd = fmaf(d0, d0, fmaf(d1, d1, d2 * d2));
        s1_l += log1pf((dd + 1e-8f) * 25.0f);        // (dist/0.2)^2
        float rc = sqrtf(dd + 1e-30f);
        bool same = (pi < 16) == (pj < 16);
        float gamma = same ? 0.25f : 0.5f;           // 1/(D+1) : 1/(D-1)
        cusp_l += gamma * rc * __expf(-rc);
    }
    #pragma unroll
    for (int s = 16; s > 0; s >>= 1) {
        r2_l   += __shfl_xor_sync(0xffffffffu, r2_l,   s);
        s1_l   += __shfl_xor_sync(0xffffffffu, s1_l,   s);
        cusp_l += __shfl_xor_sync(0xffffffffu, cusp_l, s);
    }
    if (lane == 0) {
        atomicAdd(&sred[0], r2_l);
        atomicAdd(&sred[1], s1_l);
        atomicAdd(&sred[2], cusp_l);
    }
    __syncthreads();

    // ---- assemble f_in (130) ----
    if (tid < 32) {
        float hs = 0.0f;
        #pragma unroll
        for (int i2 = 0; i2 < 32; i2++) hs += ssj[i2 * 33 + tid];
        sfin[tid]      = hs;
        sfin[32 + tid] = hs * (1.0f / 32.0f);
        float ps = spair[tid];
        sfin[64 + tid] = ps;
        sfin[96 + tid] = ps * (1.0f / 496.0f);
    }
    if (tid == 0) {
        sfin[128] = sred[0] * (1.0f / 96.0f);
        sfin[129] = sred[1] * (1.0f / 496.0f);
        sfin[130] = 0.0f;  sfin[131] = 0.0f;         // pad (unused)
    }
    __syncthreads();

    // ---- readout: 130 -> 64 (warp-cooperative, coalesced) ----
    // warp w computes outputs o = w*8 .. w*8+7
    #pragma unroll 1
    for (int oo = 0; oo < 8; oo++) {
        int o = w * 8 + oo;
        float a = 0.0f;
        // k = lane, lane+32, lane+64, lane+96, lane+128(<130)
        a = fmaf(Wf1[o * 130 + lane],      sfin[lane],      a);
        a = fmaf(Wf1[o * 130 + lane + 32], sfin[lane + 32], a);
        a = fmaf(Wf1[o * 130 + lane + 64], sfin[lane + 64], a);
        a = fmaf(Wf1[o * 130 + lane + 96], sfin[lane + 96], a);
        if (lane < 2) a = fmaf(Wf1[o * 130 + lane + 128], sfin[lane + 128], a);
        #pragma unroll
        for (int s = 16; s > 0; s >>= 1) a += __shfl_xor_sync(0xffffffffu, a, s);
        if (lane == 0) sf1[o] = silu_f(a + bf1[o]);
    }
    __syncthreads();

    // 64 -> 64
    #pragma unroll 1
    for (int oo = 0; oo < 8; oo++) {
        int o = w * 8 + oo;
        float a = fmaf(Wf2[o * 64 + lane],      sf1[lane],      0.0f);
        a       = fmaf(Wf2[o * 64 + lane + 32], sf1[lane + 32], a);
        #pragma unroll
        for (int s = 16; s > 0; s >>= 1) a += __shfl_xor_sync(0xffffffffu, a, s);
        if (lane == 0) sf2[o] = silu_f(a + bf2[o]);
    }
    __syncthreads();

    // 64 -> 1, plus cusp
    if (w == 0) {
        float a = fmaf(Wf3[lane],      sf2[lane],      0.0f);
        a       = fmaf(Wf3[lane + 32], sf2[lane + 32], a);
        #pragma unroll
        for (int s = 16; s > 0; s >>= 1) a += __shfl_xor_sync(0xffffffffu, a, s);
        if (lane == 0) out[b] = a + bf3[0] + sred[2];
    }
}

extern "C" void kernel_launch(void* const* d_in, const int* in_sizes, int n_in,
                              void* d_out, int out_size)
{
    const float* x      = (const float*)d_in[0];
    const float* W_node = (const float*)d_in[1];
    const float* b_node = (const float*)d_in[2];
    const float* We1    = (const float*)d_in[3];
    const float* be1    = (const float*)d_in[4];
    const float* We2    = (const float*)d_in[5];
    const float* be2    = (const float*)d_in[6];
    const float* Wv2e   = (const float*)d_in[7];
    const float* We2v   = (const float*)d_in[8];
    const float* Wu1    = (const float*)d_in[9];
    const float* bu1    = (const float*)d_in[10];
    const float* Wu2    = (const float*)d_in[11];
    const float* bu2    = (const float*)d_in[12];
    const float* Wn1    = (const float*)d_in[13];
    const float* bn1    = (const float*)d_in[14];
    const float* Wn2    = (const float*)d_in[15];
    const float* bn2    = (const float*)d_in[16];
    const float* Wf1    = (const float*)d_in[17];
    const float* bf1    = (const float*)d_in[18];
    const float* Wf2    = (const float*)d_in[19];
    const float* bf2    = (const float*)d_in[20];
    const float* Wf3    = (const float*)d_in[21];
    const float* bf3    = (const float*)d_in[22];

    int B = in_sizes[0] / 96;   // (B, 32, 3)
    jastrow_kernel<<<B, 256>>>(x, W_node, b_node, We1, be1, We2, be2, Wv2e, We2v,
                               Wu1, bu1, Wu2, bu2, Wn1, bn1, Wn2, bn2,
                               Wf1, bf1, Wf2, bf2, Wf3, bf3, (float*)d_out);
}

// round 3
// speedup vs baseline: 1.3703x; 1.3703x over previous
#include <cuda_runtime.h>

// CTNNBackflowStyleJastrow: B=1024, N=32, D=3, H=M=32, RH=64
// One CTA (256 threads = 8 warps) per batch element.
// Edge loop: warp-cooperative, lane = hidden channel, TWO edges per iteration.

__device__ __forceinline__ float silu_f(float x) {
    return __fdividef(x, 1.0f + __expf(-x));
}

// Dual matvec: out{0,1}[lane] = bias{0,1} + W_row(lane) . P{0,1}
#define MV2(Wr, P0, P1, o0, o1, b0, b1)                          \
{   float a00=(b0), a01=0.f, a10=(b1), a11=0.f;                  \
    _Pragma("unroll")                                            \
    for (int k = 0; k < 8; k++) {                                \
        float4 v0 = (P0)[k];                                     \
        float4 v1 = (P1)[k];                                     \
        a00 = fmaf(Wr[4*k+0], v0.x, a00);                        \
        a01 = fmaf(Wr[4*k+1], v0.y, a01);                        \
        a00 = fmaf(Wr[4*k+2], v0.z, a00);                        \
        a01 = fmaf(Wr[4*k+3], v0.w, a01);                        \
        a10 = fmaf(Wr[4*k+0], v1.x, a10);                        \
        a11 = fmaf(Wr[4*k+1], v1.y, a11);                        \
        a10 = fmaf(Wr[4*k+2], v1.z, a10);                        \
        a11 = fmaf(Wr[4*k+3], v1.w, a11);                        \
    }                                                            \
    (o0) = a00 + a01; (o1) = a10 + a11; }

__global__ __launch_bounds__(256, 1)
void jastrow_kernel(const float* __restrict__ x,
                    const float* __restrict__ W_node, const float* __restrict__ b_node,
                    const float* __restrict__ We1,  const float* __restrict__ be1,
                    const float* __restrict__ We2,  const float* __restrict__ be2,
                    const float* __restrict__ Wv2e, const float* __restrict__ We2v,
                    const float* __restrict__ Wu1,  const float* __restrict__ bu1,
                    const float* __restrict__ Wu2,  const float* __restrict__ bu2,
                    const float* __restrict__ Wn1,  const float* __restrict__ bn1,
                    const float* __restrict__ Wn2,  const float* __restrict__ bn2,
                    const float* __restrict__ Wf1,  const float* __restrict__ bf1,
                    const float* __restrict__ Wf2,  const float* __restrict__ bf2,
                    const float* __restrict__ Wf3,  const float* __restrict__ bf3,
                    float* __restrict__ out)
{
    __shared__ float sx[96];           // x for this batch (OMEGA = 1 so x_sc == x)
    __shared__ float shv[32 * 33];     // h_v (pre-update), [i*33 + h]
    __shared__ float sp [32 * 33];     // p, later m_v
    __shared__ float sq [32 * 33];     // q_i, later a1
    __shared__ float ssj[32 * 33];     // s_j, later h_v_new
    __shared__ float srs[32 * 33];     // weight staging scratch, then row sums of h_e_new
    __shared__ float spair[32];        // sum over i<j of (h_e + h_e_new)
    __shared__ float sred[3];          // r2_sum, s1_sum, cusp_sum
    __shared__ float sfin[132], sf1[64], sf2[64];
    __shared__ __align__(16) float sbuf[8 * 128];   // per-warp staging A0|A1|B0|B1 (32 each)
    __shared__ __align__(16) float sfeat[8 * 256];  // per-warp edge features [j*8 + c]

    const int tid  = threadIdx.x;
    const int lane = tid & 31;
    const int w    = tid >> 5;
    const int b    = blockIdx.x;

    if (tid < 96) sx[tid] = x[b * 96 + tid];
    if (tid < 32) spair[tid] = 0.0f;
    if (tid < 3)  sred[tid] = 0.0f;
    __syncthreads();

    // ---- node phases: lane = node index i, (warp,iter) = channel ----
    #pragma unroll
    for (int it = 0; it < 4; it++) {
        int ch = w + it * 8;
        int i  = lane;
        float sf = (i >= 16) ? 1.0f : 0.0f;
        float a = b_node[ch]
                + W_node[ch * 4 + 0] * sx[i * 3 + 0]
                + W_node[ch * 4 + 1] * sx[i * 3 + 1]
                + W_node[ch * 4 + 2] * sx[i * 3 + 2]
                + W_node[ch * 4 + 3] * sf;
        shv[i * 33 + ch] = a;
    }
    __syncthreads();

    // p = h_v @ Wv2e^T
    #pragma unroll
    for (int it = 0; it < 4; it++) {
        int m = w + it * 8;
        int i = lane;
        float a0 = 0.f, a1 = 0.f;
        #pragma unroll
        for (int h = 0; h < 32; h += 2) {
            a0 = fmaf(Wv2e[m * 32 + h + 0], shv[i * 33 + h + 0], a0);
            a1 = fmaf(Wv2e[m * 32 + h + 1], shv[i * 33 + h + 1], a1);
        }
        sp[i * 33 + m] = a0 + a1;
    }
    __syncthreads();

    // q_i = Wu1[:,32:64]@p_i + bu1 ; s_j = Wu1[:,64:96]@p_j
    #pragma unroll
    for (int it = 0; it < 4; it++) {
        int h = w + it * 8;
        int i = lane;
        float aq = bu1[h], as = 0.f;
        #pragma unroll
        for (int m = 0; m < 32; m++) {
            float pv = sp[i * 33 + m];
            aq = fmaf(Wu1[h * 96 + 32 + m], pv, aq);
            as = fmaf(Wu1[h * 96 + 64 + m], pv, as);
        }
        sq [i * 33 + h] = aq;
        ssj[i * 33 + h] = as;
    }

    // ---- per-lane weight rows, staged transposed through srs (scratch) ----
    float We2r[32], Wu1r[32], Wu2r[32];
    __syncthreads();
    for (int idx = tid; idx < 1024; idx += 256) {
        int r = idx >> 5, k = idx & 31;
        srs[k * 33 + r] = We2[r * 32 + k];
    }
    __syncthreads();
    #pragma unroll
    for (int k = 0; k < 32; k++) We2r[k] = srs[k * 33 + lane];
    __syncthreads();
    for (int idx = tid; idx < 1024; idx += 256) {
        int r = idx >> 5, k = idx & 31;
        srs[k * 33 + r] = Wu1[r * 96 + k];
    }
    __syncthreads();
    #pragma unroll
    for (int k = 0; k < 32; k++) Wu1r[k] = srs[k * 33 + lane];
    __syncthreads();
    for (int idx = tid; idx < 1024; idx += 256) {
        int r = idx >> 5, k = idx & 31;
        srs[k * 33 + r] = Wu2[r * 32 + k];
    }
    __syncthreads();
    #pragma unroll
    for (int k = 0; k < 32; k++) Wu2r[k] = srs[k * 33 + lane];
    __syncthreads();

    const float We1r0 = We1[lane * 5 + 0], We1r1 = We1[lane * 5 + 1], We1r2 = We1[lane * 5 + 2];
    const float We1r3 = We1[lane * 5 + 3], We1r4 = We1[lane * 5 + 4];
    const float be1r = be1[lane], be2r = be2[lane], bu2r = bu2[lane];

    float* bufA0 = &sbuf[w * 128];
    float* bufA1 = &sbuf[w * 128 + 32];
    float* bufB0 = &sbuf[w * 128 + 64];
    float* bufB1 = &sbuf[w * 128 + 96];
    const float4* A04 = reinterpret_cast<const float4*>(bufA0);
    const float4* A14 = reinterpret_cast<const float4*>(bufA1);
    const float4* B04 = reinterpret_cast<const float4*>(bufB0);
    const float4* B14 = reinterpret_cast<const float4*>(bufB1);
    float*        featf = &sfeat[w * 256];
    const float4* feat4 = reinterpret_cast<const float4*>(featf);

    float pacc = 0.0f;

    // ---- edge loop: warp w owns rows i = 4w..4w+3; lane = channel ----
    #pragma unroll 1
    for (int ii = 0; ii < 4; ii++) {
        const int i = w * 4 + ii;
        const float xi0 = sx[i * 3 + 0], xi1 = sx[i * 3 + 1], xi2 = sx[i * 3 + 2];
        const float qv  = sq[i * 33 + lane];
        float racc = 0.0f;

        // features for all 32 j in one lane-parallel pass (lane = j)
        {
            int j = lane;
            float fr0 = xi0 - sx[j * 3 + 0];
            float fr1 = xi1 - sx[j * 3 + 1];
            float fr2 = xi2 - sx[j * 3 + 2];
            float frr2 = fmaf(fr0, fr0, fmaf(fr1, fr1, fr2 * fr2));
            float tpl = frr2 + 1e-12f;
            float frr1 = tpl * __frsqrt_rn(tpl);
            __syncwarp();              // prior ii's readers of sfeat done
            reinterpret_cast<float4*>(featf)[j * 2] = make_float4(fr0, fr1, fr2, frr1);
            featf[j * 8 + 4] = frr2;
            __syncwarp();
        }

        #pragma unroll 1
        for (int jp = 0; jp < 16; jp++) {
            const int j0 = jp, j1 = jp + 16;

            float4 fe0 = feat4[j0 * 2]; float rr20 = featf[j0 * 8 + 4];
            float4 fe1 = feat4[j1 * 2]; float rr21 = featf[j1 * 8 + 4];

            // layer e1 (lane h)
            float tt0 = be1r, tt1 = be1r;
            tt0 = fmaf(We1r0, fe0.x, tt0);  tt1 = fmaf(We1r0, fe1.x, tt1);
            tt0 = fmaf(We1r1, fe0.y, tt0);  tt1 = fmaf(We1r1, fe1.y, tt1);
            tt0 = fmaf(We1r2, fe0.z, tt0);  tt1 = fmaf(We1r2, fe1.z, tt1);
            tt0 = fmaf(We1r3, fe0.w, tt0);  tt1 = fmaf(We1r3, fe1.w, tt1);
            tt0 = fmaf(We1r4, rr20, tt0);   tt1 = fmaf(We1r4, rr21, tt1);
            tt0 = silu_f(tt0);              tt1 = silu_f(tt1);

            __syncwarp();                  // prior iter's hn-stage reads of A done
            bufA0[lane] = tt0; bufA1[lane] = tt1;
            __syncwarp();

            // h_e (lane c)
            float he0, he1;
            MV2(We2r, A04, A14, he0, he1, be2r, be2r);
            bufB0[lane] = he0; bufB1[lane] = he1;
            __syncwarp();

            // t2 (lane h) = silu(q_i + s_j + Wu1a . h_e)
            float s0 = qv + ssj[j0 * 33 + lane];
            float s1 = qv + ssj[j1 * 33 + lane];
            float t20, t21;
            MV2(Wu1r, B04, B14, t20, t21, s0, s1);
            t20 = silu_f(t20); t21 = silu_f(t21);
            bufA0[lane] = t20; bufA1[lane] = t21;   // A consumed by he-stage (pre-B sync)
            __syncwarp();

            // h_e_new (lane c)
            float hn0, hn1;
            MV2(Wu2r, A04, A14, hn0, hn1, bu2r, bu2r);

            if (i != j0) racc += hn0;
            if (i != j1) racc += hn1;
            if (i < j0)  pacc += he0 + hn0;
            if (i < j1)  pacc += he1 + hn1;
        }
        srs[i * 33 + lane] = racc;     // warp-exclusive row: no atomics
    }
    atomicAdd(&spair[lane], pacc);
    __syncthreads();

    // ---- m_v = We2v @ rowsum  (reuse sp) ----
    #pragma unroll
    for (int it = 0; it < 4; it++) {
        int h = w + it * 8;
        int i = lane;
        float a0 = 0.f, a1 = 0.f;
        #pragma unroll
        for (int c = 0; c < 32; c += 2) {
            a0 = fmaf(We2v[h * 32 + c + 0], srs[i * 33 + c + 0], a0);
            a1 = fmaf(We2v[h * 32 + c + 1], srs[i * 33 + c + 1], a1);
        }
        sp[i * 33 + h] = a0 + a1;
    }
    __syncthreads();

    // ---- a1 = silu(Wn1 @ [h_v, m_v] + bn1)  (reuse sq) ----
    #pragma unroll
    for (int it = 0; it < 4; it++) {
        int h = w + it * 8;
        int i = lane;
        float a = bn1[h];
        #pragma unroll
        for (int k = 0; k < 32; k++) a = fmaf(Wn1[h * 64 + k],      shv[i * 33 + k], a);
        #pragma unroll
        for (int k = 0; k < 32; k++) a = fmaf(Wn1[h * 64 + 32 + k], sp [i * 33 + k], a);
        sq[i * 33 + h] = silu_f(a);
    }
    __syncthreads();

    // ---- h_v_new = h_v + Wn2 @ a1 + bn2  (reuse ssj) ----
    #pragma unroll
    for (int it = 0; it < 4; it++) {
        int h = w + it * 8;
        int i = lane;
        float a = shv[i * 33 + h] + bn2[h];
        #pragma unroll
        for (int c = 0; c < 32; c++) a = fmaf(Wn2[h * 32 + c], sq[i * 33 + c], a);
        ssj[i * 33 + h] = a;
    }

    // ---- pairwise scalars: r2_sum, s1_sum, cusp ----
    float r2_l = 0.0f, s1_l = 0.0f, cusp_l = 0.0f;
    if (tid < 96) r2_l = sx[tid] * sx[tid];
    for (int idx = tid; idx < 496; idx += 256) {
        int rem = idx, pi = 0, cnt = 31;
        while (rem >= cnt) { rem -= cnt; pi++; cnt--; }
        int pj = pi + 1 + rem;
        float d0 = sx[pi * 3 + 0] - sx[pj * 3 + 0];
        float d1 = sx[pi * 3 + 1] - sx[pj * 3 + 1];
        float d2 = sx[pi * 3 + 2] - sx[pj * 3 + 2];
        float dd = fmaf(d0, d0, fmaf(d1, d1, d2 * d2));
        s1_l += log1pf((dd + 1e-8f) * 25.0f);        // (dist/0.2)^2
        float rc = sqrtf(dd + 1e-30f);
        bool same = (pi < 16) == (pj < 16);
        float gamma = same ? 0.25f : 0.5f;           // 1/(D+1) : 1/(D-1)
        cusp_l += gamma * rc * __expf(-rc);
    }
    #pragma unroll
    for (int s = 16; s > 0; s >>= 1) {
        r2_l   += __shfl_xor_sync(0xffffffffu, r2_l,   s);
        s1_l   += __shfl_xor_sync(0xffffffffu, s1_l,   s);
        cusp_l += __shfl_xor_sync(0xffffffffu, cusp_l, s);
    }
    if (lane == 0) {
        atomicAdd(&sred[0], r2_l);
        atomicAdd(&sred[1], s1_l);
        atomicAdd(&sred[2], cusp_l);
    }
    __syncthreads();

    // ---- assemble f_in (130) ----
    if (tid < 32) {
        float hs = 0.0f;
        #pragma unroll
        for (int i2 = 0; i2 < 32; i2++) hs += ssj[i2 * 33 + tid];
        sfin[tid]      = hs;
        sfin[32 + tid] = hs * (1.0f / 32.0f);
        float ps = spair[tid];
        sfin[64 + tid] = ps;
        sfin[96 + tid] = ps * (1.0f / 496.0f);
    }
    if (tid == 0) {
        sfin[128] = sred[0] * (1.0f / 96.0f);
        sfin[129] = sred[1] * (1.0f / 496.0f);
        sfin[130] = 0.0f;  sfin[131] = 0.0f;
    }
    __syncthreads();

    // ---- readout: 130 -> 64 -> 64 -> 1 ----
    #pragma unroll 1
    for (int oo = 0; oo < 8; oo++) {
        int o = w * 8 + oo;
        float a = 0.0f;
        a = fmaf(Wf1[o * 130 + lane],      sfin[lane],      a);
        a = fmaf(Wf1[o * 130 + lane + 32], sfin[lane + 32], a);
        a = fmaf(Wf1[o * 130 + lane + 64], sfin[lane + 64], a);
        a = fmaf(Wf1[o * 130 + lane + 96], sfin[lane + 96], a);
        if (lane < 2) a = fmaf(Wf1[o * 130 + lane + 128], sfin[lane + 128], a);
        #pragma unroll
        for (int s = 16; s > 0; s >>= 1) a += __shfl_xor_sync(0xffffffffu, a, s);
        if (lane == 0) sf1[o] = silu_f(a + bf1[o]);
    }
    __syncthreads();

    #pragma unroll 1
    for (int oo = 0; oo < 8; oo++) {
        int o = w * 8 + oo;
        float a = fmaf(Wf2[o * 64 + lane],      sf1[lane],      0.0f);
        a       = fmaf(Wf2[o * 64 + lane + 32], sf1[lane + 32], a);
        #pragma unroll
        for (int s = 16; s > 0; s >>= 1) a += __shfl_xor_sync(0xffffffffu, a, s);
        if (lane == 0) sf2[o] = silu_f(a + bf2[o]);
    }
    __syncthreads();

    if (w == 0) {
        float a = fmaf(Wf3[lane],      sf2[lane],      0.0f);
        a       = fmaf(Wf3[lane + 32], sf2[lane + 32], a);
        #pragma unroll
        for (int s = 16; s > 0; s >>= 1) a += __shfl_xor_sync(0xffffffffu, a, s);
        if (lane == 0) out[b] = a + bf3[0] + sred[2];
    }
}

extern "C" void kernel_launch(void* const* d_in, const int* in_sizes, int n_in,
                              void* d_out, int out_size)
{
    const float* x      = (const float*)d_in[0];
    const float* W_node = (const float*)d_in[1];
    const float* b_node = (const float*)d_in[2];
    const float* We1    = (const float*)d_in[3];
    const float* be1    = (const float*)d_in[4];
    const float* We2    = (const float*)d_in[5];
    const float* be2    = (const float*)d_in[6];
    const float* Wv2e   = (const float*)d_in[7];
    const float* We2v   = (const float*)d_in[8];
    const float* Wu1    = (const float*)d_in[9];
    const float* bu1    = (const float*)d_in[10];
    const float* Wu2    = (const float*)d_in[11];
    const float* bu2    = (const float*)d_in[12];
    const float* Wn1    = (const float*)d_in[13];
    const float* bn1    = (const float*)d_in[14];
    const float* Wn2    = (const float*)d_in[15];
    const float* bn2    = (const float*)d_in[16];
    const float* Wf1    = (const float*)d_in[17];
    const float* bf1    = (const float*)d_in[18];
    const float* Wf2    = (const float*)d_in[19];
    const float* bf2    = (const float*)d_in[20];
    const float* Wf3    = (const float*)d_in[21];
    const float* bf3    = (const float*)d_in[22];

    int B = in_sizes[0] / 96;   // (B, 32, 3)
    jastrow_kernel<<<B, 256>>>(x, W_node, b_node, We1, be1, We2, be2, Wv2e, We2v,
                               Wu1, bu1, Wu2, bu2, Wn1, bn1, Wn2, bn2,
                               Wf1, bf1, Wf2, bf2, Wf3, bf3, (float*)d_out);
}

// round 4
// speedup vs baseline: 1.4081x; 1.0276x over previous
#include <cuda_runtime.h>
#include <cstdint>

// CTNNBackflowStyleJastrow: B=1024, N=32, D=3, H=M=32, RH=64
// One CTA (256 threads = 8 warps) per batch element.
// Edge loop: warp-cooperative, lane = hidden channel, TWO edges per iteration,
// matvecs via packed fma.rn.f32x2 (sm_100+), activations read as ld.shared.v2.b64.

__device__ __forceinline__ float silu_f(float x) {
    return __fdividef(x, 1.0f + __expf(-x));
}

__device__ __forceinline__ unsigned long long pack2(float lo, float hi) {
    unsigned long long r;
    asm("mov.b64 %0, {%1, %2};" : "=l"(r) : "f"(lo), "f"(hi));
    return r;
}
__device__ __forceinline__ unsigned long long fma2(unsigned long long a,
                                                   unsigned long long b,
                                                   unsigned long long c) {
    unsigned long long d;
    asm("fma.rn.f32x2 %0, %1, %2, %3;" : "=l"(d) : "l"(a), "l"(b), "l"(c));
    return d;
}
__device__ __forceinline__ float unpack_sum2(unsigned long long a, unsigned long long b) {
    float al, ah, bl, bh;
    asm("mov.b64 {%0, %1}, %2;" : "=f"(al), "=f"(ah) : "l"(a));
    asm("mov.b64 {%0, %1}, %2;" : "=f"(bl), "=f"(bh) : "l"(b));
    return (al + ah) + (bl + bh);
}
__device__ __forceinline__ void lds_v2u64(uint32_t addr,
                                          unsigned long long& p0, unsigned long long& p1) {
    asm volatile("ld.shared.v2.b64 {%0, %1}, [%2];" : "=l"(p0), "=l"(p1) : "r"(addr));
}

// Dual-edge packed matvec: o{0,1} = bias{0,1} + W_row(lane) . smem_vec{0,1}
#define MV2P(Wp, addr0, addr1, o0, o1, bias0, bias1)                \
{   unsigned long long A00 = pack2((bias0), 0.0f), A01 = 0ULL;      \
    unsigned long long A10 = pack2((bias1), 0.0f), A11 = 0ULL;      \
    _Pragma("unroll")                                               \
    for (int g = 0; g < 8; g++) {                                   \
        unsigned long long p0, p1, q0, q1;                          \
        lds_v2u64((addr0) + g * 16, p0, p1);                        \
        lds_v2u64((addr1) + g * 16, q0, q1);                        \
        A00 = fma2(Wp[2*g],   p0, A00);                             \
        A01 = fma2(Wp[2*g+1], p1, A01);                             \
        A10 = fma2(Wp[2*g],   q0, A10);                             \
        A11 = fma2(Wp[2*g+1], q1, A11);                             \
    }                                                               \
    (o0) = unpack_sum2(A00, A01);                                   \
    (o1) = unpack_sum2(A10, A11); }

__global__ __launch_bounds__(256, 1)
void jastrow_kernel(const float* __restrict__ x,
                    const float* __restrict__ W_node, const float* __restrict__ b_node,
                    const float* __restrict__ We1,  const float* __restrict__ be1,
                    const float* __restrict__ We2,  const float* __restrict__ be2,
                    const float* __restrict__ Wv2e, const float* __restrict__ We2v,
                    const float* __restrict__ Wu1,  const float* __restrict__ bu1,
                    const float* __restrict__ Wu2,  const float* __restrict__ bu2,
                    const float* __restrict__ Wn1,  const float* __restrict__ bn1,
                    const float* __restrict__ Wn2,  const float* __restrict__ bn2,
                    const float* __restrict__ Wf1,  const float* __restrict__ bf1,
                    const float* __restrict__ Wf2,  const float* __restrict__ bf2,
                    const float* __restrict__ Wf3,  const float* __restrict__ bf3,
                    float* __restrict__ out)
{
    __shared__ float sx[96];
    __shared__ float shv[32 * 33];     // h_v (pre-update)
    __shared__ float sp [32 * 33];     // p, later m_v
    __shared__ float sq [32 * 33];     // q_i, later a1
    __shared__ float ssj[32 * 33];     // s_j, later h_v_new
    __shared__ float srs[32 * 33];     // weight staging scratch, then row sums
    __shared__ float spair[32];
    __shared__ float sred[3];
    __shared__ float sfin[132], sf1[64], sf2[64];
    // per-warp staging: A[2 sets][2 edges][32] + B[2 edges][32] = 192 floats
    __shared__ __align__(16) float sbuf[8 * 192];
    __shared__ __align__(16) float sfeat[8 * 256];  // per-warp edge features [j*8 + c]

    const int tid  = threadIdx.x;
    const int lane = tid & 31;
    const int w    = tid >> 5;
    const int b    = blockIdx.x;

    if (tid < 96) sx[tid] = x[b * 96 + tid];
    if (tid < 32) spair[tid] = 0.0f;
    if (tid < 3)  sred[tid] = 0.0f;
    __syncthreads();

    // ---- node phases: lane = node index i, (warp,iter) = channel ----
    #pragma unroll
    for (int it = 0; it < 4; it++) {
        int ch = w + it * 8;
        int i  = lane;
        float sf = (i >= 16) ? 1.0f : 0.0f;
        float a = b_node[ch]
                + W_node[ch * 4 + 0] * sx[i * 3 + 0]
                + W_node[ch * 4 + 1] * sx[i * 3 + 1]
                + W_node[ch * 4 + 2] * sx[i * 3 + 2]
                + W_node[ch * 4 + 3] * sf;
        shv[i * 33 + ch] = a;
    }
    __syncthreads();

    // p = h_v @ Wv2e^T
    #pragma unroll
    for (int it = 0; it < 4; it++) {
        int m = w + it * 8;
        int i = lane;
        float a0 = 0.f, a1 = 0.f;
        #pragma unroll
        for (int h = 0; h < 32; h += 2) {
            a0 = fmaf(Wv2e[m * 32 + h + 0], shv[i * 33 + h + 0], a0);
            a1 = fmaf(Wv2e[m * 32 + h + 1], shv[i * 33 + h + 1], a1);
        }
        sp[i * 33 + m] = a0 + a1;
    }
    __syncthreads();

    // q_i = Wu1[:,32:64]@p_i + bu1 ; s_j = Wu1[:,64:96]@p_j
    #pragma unroll
    for (int it = 0; it < 4; it++) {
        int h = w + it * 8;
        int i = lane;
        float aq = bu1[h], as = 0.f;
        #pragma unroll
        for (int m = 0; m < 32; m++) {
            float pv = sp[i * 33 + m];
            aq = fmaf(Wu1[h * 96 + 32 + m], pv, aq);
            as = fmaf(Wu1[h * 96 + 64 + m], pv, as);
        }
        sq [i * 33 + h] = aq;
        ssj[i * 33 + h] = as;
    }

    // ---- per-lane PACKED weight rows, staged transposed through srs ----
    unsigned long long We2p[16], Wu1p[16], Wu2p[16];
    __syncthreads();
    for (int idx = tid; idx < 1024; idx += 256) {
        int r = idx >> 5, k = idx & 31;
        srs[k * 33 + r] = We2[r * 32 + k];
    }
    __syncthreads();
    #pragma unroll
    for (int g = 0; g < 16; g++)
        We2p[g] = pack2(srs[(2 * g) * 33 + lane], srs[(2 * g + 1) * 33 + lane]);
    __syncthreads();
    for (int idx = tid; idx < 1024; idx += 256) {
        int r = idx >> 5, k = idx & 31;
        srs[k * 33 + r] = Wu1[r * 96 + k];
    }
    __syncthreads();
    #pragma unroll
    for (int g = 0; g < 16; g++)
        Wu1p[g] = pack2(srs[(2 * g) * 33 + lane], srs[(2 * g + 1) * 33 + lane]);
    __syncthreads();
    for (int idx = tid; idx < 1024; idx += 256) {
        int r = idx >> 5, k = idx & 31;
        srs[k * 33 + r] = Wu2[r * 32 + k];
    }
    __syncthreads();
    #pragma unroll
    for (int g = 0; g < 16; g++)
        Wu2p[g] = pack2(srs[(2 * g) * 33 + lane], srs[(2 * g + 1) * 33 + lane]);
    __syncthreads();

    const float We1r0 = We1[lane * 5 + 0], We1r1 = We1[lane * 5 + 1], We1r2 = We1[lane * 5 + 2];
    const float We1r3 = We1[lane * 5 + 3], We1r4 = We1[lane * 5 + 4];
    const float be1r = be1[lane], be2r = be2[lane], bu2r = bu2[lane];

    // smem byte addresses for asm loads
    float* warpbuf = &sbuf[w * 192];
    const uint32_t sbA  = (uint32_t)__cvta_generic_to_shared(warpbuf);           // A sets: +0, +256B
    const uint32_t sbB0 = sbA + 512;                                             // B0
    const uint32_t sbB1 = sbA + 640;                                             // B1
    float* featf = &sfeat[w * 256];
    const float4* feat4 = reinterpret_cast<const float4*>(featf);

    float pacc = 0.0f;

    // ---- edge loop: warp w owns rows i = 4w..4w+3; lane = channel ----
    #pragma unroll 1
    for (int ii = 0; ii < 4; ii++) {
        const int i = w * 4 + ii;
        const float xi0 = sx[i * 3 + 0], xi1 = sx[i * 3 + 1], xi2 = sx[i * 3 + 2];
        const float qv  = sq[i * 33 + lane];
        float racc = 0.0f;

        // features for all 32 j in one lane-parallel pass (lane = j)
        {
            int j = lane;
            float fr0 = xi0 - sx[j * 3 + 0];
            float fr1 = xi1 - sx[j * 3 + 1];
            float fr2 = xi2 - sx[j * 3 + 2];
            float frr2 = fmaf(fr0, fr0, fmaf(fr1, fr1, fr2 * fr2));
            float tpl = frr2 + 1e-12f;
            float frr1 = tpl * __frsqrt_rn(tpl);
            __syncwarp();
            reinterpret_cast<float4*>(featf)[j * 2] = make_float4(fr0, fr1, fr2, frr1);
            featf[j * 8 + 4] = frr2;
            __syncwarp();
        }

        #pragma unroll 1
        for (int jp = 0; jp < 16; jp++) {
            const int j0 = jp, j1 = jp + 16;
            const int p  = jp & 1;
            float* bufA0 = warpbuf + p * 64;
            float* bufA1 = bufA0 + 32;
            float* bufB0 = warpbuf + 128;
            float* bufB1 = warpbuf + 160;
            const uint32_t aA0 = sbA + p * 256;
            const uint32_t aA1 = aA0 + 128;

            float4 fe0 = feat4[j0 * 2]; float rr20 = featf[j0 * 8 + 4];
            float4 fe1 = feat4[j1 * 2]; float rr21 = featf[j1 * 8 + 4];

            // layer e1 (lane h)
            float tt0 = be1r, tt1 = be1r;
            tt0 = fmaf(We1r0, fe0.x, tt0);  tt1 = fmaf(We1r0, fe1.x, tt1);
            tt0 = fmaf(We1r1, fe0.y, tt0);  tt1 = fmaf(We1r1, fe1.y, tt1);
            tt0 = fmaf(We1r2, fe0.z, tt0);  tt1 = fmaf(We1r2, fe1.z, tt1);
            tt0 = fmaf(We1r3, fe0.w, tt0);  tt1 = fmaf(We1r3, fe1.w, tt1);
            tt0 = fmaf(We1r4, rr20, tt0);   tt1 = fmaf(We1r4, rr21, tt1);
            tt0 = silu_f(tt0);              tt1 = silu_f(tt1);

            // ping-pong A set: prior use of this set was 2 barriers ago -> safe, no top sync
            bufA0[lane] = tt0; bufA1[lane] = tt1;
            __syncwarp();

            // h_e (lane c)
            float he0, he1;
            MV2P(We2p, aA0, aA1, he0, he1, be2r, be2r);
            bufB0[lane] = he0; bufB1[lane] = he1;
            __syncwarp();

            // t2 (lane h) = silu(q_i + s_j + Wu1a . h_e)
            float s0 = qv + ssj[j0 * 33 + lane];
            float s1 = qv + ssj[j1 * 33 + lane];
            float t20, t21;
            MV2P(Wu1p, sbB0, sbB1, t20, t21, s0, s1);
            t20 = silu_f(t20); t21 = silu_f(t21);
            bufA0[lane] = t20; bufA1[lane] = t21;   // A reads (he stage) done before B sync
            __syncwarp();

            // h_e_new (lane c)
            float hn0, hn1;
            MV2P(Wu2p, aA0, aA1, hn0, hn1, bu2r, bu2r);

            if (i != j0) racc += hn0;
            if (i != j1) racc += hn1;
            if (i < j0)  pacc += he0 + hn0;
            if (i < j1)  pacc += he1 + hn1;
        }
        srs[i * 33 + lane] = racc;     // warp-exclusive row: no atomics
    }
    atomicAdd(&spair[lane], pacc);
    __syncthreads();

    // ---- m_v = We2v @ rowsum  (reuse sp) ----
    #pragma unroll
    for (int it = 0; it < 4; it++) {
        int h = w + it * 8;
        int i = lane;
        float a0 = 0.f, a1 = 0.f;
        #pragma unroll
        for (int c = 0; c < 32; c += 2) {
            a0 = fmaf(We2v[h * 32 + c + 0], srs[i * 33 + c + 0], a0);
            a1 = fmaf(We2v[h * 32 + c + 1], srs[i * 33 + c + 1], a1);
        }
        sp[i * 33 + h] = a0 + a1;
    }
    __syncthreads();

    // ---- a1 = silu(Wn1 @ [h_v, m_v] + bn1)  (reuse sq) ----
    #pragma unroll
    for (int it = 0; it < 4; it++) {
        int h = w + it * 8;
        int i = lane;
        float a = bn1[h];
        #pragma unroll
        for (int k = 0; k < 32; k++) a = fmaf(Wn1[h * 64 + k],      shv[i * 33 + k], a);
        #pragma unroll
        for (int k = 0; k < 32; k++) a = fmaf(Wn1[h * 64 + 32 + k], sp [i * 33 + k], a);
        sq[i * 33 + h] = silu_f(a);
    }
    __syncthreads();

    // ---- h_v_new = h_v + Wn2 @ a1 + bn2  (reuse ssj) ----
    #pragma unroll
    for (int it = 0; it < 4; it++) {
        int h = w + it * 8;
        int i = lane;
        float a = shv[i * 33 + h] + bn2[h];
        #pragma unroll
        for (int c = 0; c < 32; c++) a = fmaf(Wn2[h * 32 + c], sq[i * 33 + c], a);
        ssj[i * 33 + h] = a;
    }

    // ---- pairwise scalars: r2_sum, s1_sum, cusp ----
    float r2_l = 0.0f, s1_l = 0.0f, cusp_l = 0.0f;
    if (tid < 96) r2_l = sx[tid] * sx[tid];
    for (int idx = tid; idx < 496; idx += 256) {
        int rem = idx, pi = 0, cnt = 31;
        while (rem >= cnt) { rem -= cnt; pi++; cnt--; }
        int pj = pi + 1 + rem;
        float d0 = sx[pi * 3 + 0] - sx[pj * 3 + 0];
        float d1 = sx[pi * 3 + 1] - sx[pj * 3 + 1];
        float d2 = sx[pi * 3 + 2] - sx[pj * 3 + 2];
        float dd = fmaf(d0, d0, fmaf(d1, d1, d2 * d2));
        s1_l += log1pf((dd + 1e-8f) * 25.0f);
        float rc = sqrtf(dd + 1e-30f);
        bool same = (pi < 16) == (pj < 16);
        float gamma = same ? 0.25f : 0.5f;
        cusp_l += gamma * rc * __expf(-rc);
    }
    #pragma unroll
    for (int s = 16; s > 0; s >>= 1) {
        r2_l   += __shfl_xor_sync(0xffffffffu, r2_l,   s);
        s1_l   += __shfl_xor_sync(0xffffffffu, s1_l,   s);
        cusp_l += __shfl_xor_sync(0xffffffffu, cusp_l, s);
    }
    if (lane == 0) {
        atomicAdd(&sred[0], r2_l);
        atomicAdd(&sred[1], s1_l);
        atomicAdd(&sred[2], cusp_l);
    }
    __syncthreads();

    // ---- assemble f_in (130) ----
    if (tid < 32) {
        float hs = 0.0f;
        #pragma unroll
        for (int i2 = 0; i2 < 32; i2++) hs += ssj[i2 * 33 + tid];
        sfin[tid]      = hs;
        sfin[32 + tid] = hs * (1.0f / 32.0f);
        float ps = spair[tid];
        sfin[64 + tid] = ps;
        sfin[96 + tid] = ps * (1.0f / 496.0f);
    }
    if (tid == 0) {
        sfin[128] = sred[0] * (1.0f / 96.0f);
        sfin[129] = sred[1] * (1.0f / 496.0f);
        sfin[130] = 0.0f;  sfin[131] = 0.0f;
    }
    __syncthreads();

    // ---- readout: 130 -> 64 -> 64 -> 1 ----
    #pragma unroll 1
    for (int oo = 0; oo < 8; oo++) {
        int o = w * 8 + oo;
        float a = 0.0f;
        a = fmaf(Wf1[o * 130 + lane],      sfin[lane],      a);
        a = fmaf(Wf1[o * 130 + lane + 32], sfin[lane + 32], a);
        a = fmaf(Wf1[o * 130 + lane + 64], sfin[lane + 64], a);
        a = fmaf(Wf1[o * 130 + lane + 96], sfin[lane + 96], a);
        if (lane < 2) a = fmaf(Wf1[o * 130 + lane + 128], sfin[lane + 128], a);
        #pragma unroll
        for (int s = 16; s > 0; s >>= 1) a += __shfl_xor_sync(0xffffffffu, a, s);
        if (lane == 0) sf1[o] = silu_f(a + bf1[o]);
    }
    __syncthreads();

    #pragma unroll 1
    for (int oo = 0; oo < 8; oo++) {
        int o = w * 8 + oo;
        float a = fmaf(Wf2[o * 64 + lane],      sf1[lane],      0.0f);
        a       = fmaf(Wf2[o * 64 + lane + 32], sf1[lane + 32], a);
        #pragma unroll
        for (int s = 16; s > 0; s >>= 1) a += __shfl_xor_sync(0xffffffffu, a, s);
        if (lane == 0) sf2[o] = silu_f(a + bf2[o]);
    }
    __syncthreads();

    if (w == 0) {
        float a = fmaf(Wf3[lane],      sf2[lane],      0.0f);
        a       = fmaf(Wf3[lane + 32], sf2[lane + 32], a);
        #pragma unroll
        for (int s = 16; s > 0; s >>= 1) a += __shfl_xor_sync(0xffffffffu, a, s);
        if (lane == 0) out[b] = a + bf3[0] + sred[2];
    }
}

extern "C" void kernel_launch(void* const* d_in, const int* in_sizes, int n_in,
                              void* d_out, int out_size)
{
    const float* x      = (const float*)d_in[0];
    const float* W_node = (const float*)d_in[1];
    const float* b_node = (const float*)d_in[2];
    const float* We1    = (const float*)d_in[3];
    const float* be1    = (const float*)d_in[4];
    const float* We2    = (const float*)d_in[5];
    const float* be2    = (const float*)d_in[6];
    const float* Wv2e   = (const float*)d_in[7];
    const float* We2v   = (const float*)d_in[8];
    const float* Wu1    = (const float*)d_in[9];
    const float* bu1    = (const float*)d_in[10];
    const float* Wu2    = (const float*)d_in[11];
    const float* bu2    = (const float*)d_in[12];
    const float* Wn1    = (const float*)d_in[13];
    const float* bn1    = (const float*)d_in[14];
    const float* Wn2    = (const float*)d_in[15];
    const float* bn2    = (const float*)d_in[16];
    const float* Wf1    = (const float*)d_in[17];
    const float* bf1    = (const float*)d_in[18];
    const float* Wf2    = (const float*)d_in[19];
    const float* bf2    = (const float*)d_in[20];
    const float* Wf3    = (const float*)d_in[21];
    const float* bf3    = (const float*)d_in[22];

    int B = in_sizes[0] / 96;   // (B, 32, 3)
    jastrow_kernel<<<B, 256>>>(x, W_node, b_node, We1, be1, We2, be2, Wv2e, We2v,
                               Wu1, bu1, Wu2, bu2, Wn1, bn1, Wn2, bn2,
                               Wf1, bf1, Wf2, bf2, Wf3, bf3, (float*)d_out);
}

// round 6
// speedup vs baseline: 1.5003x; 1.0655x over previous
#include <cuda_runtime.h>
#include <cstdint>

// CTNNBackflowStyleJastrow: B=1024, N=32, D=3, H=M=32, RH=64
// One CTA (256 threads = 8 warps) per batch element.
// Edge loop: lane = edge j, warp processes one full row i (32 edges) at a time.
// Activations stay in registers (packed f32x2); weights broadcast from smem.
// No syncwarp/STS inside the per-edge pipeline.

__device__ __forceinline__ float silu_f(float x) {
    return __fdividef(x, 1.0f + __expf(-x));
}
__device__ __forceinline__ unsigned long long pack2(float lo, float hi) {
    unsigned long long r;
    asm("mov.b64 %0, {%1, %2};" : "=l"(r) : "f"(lo), "f"(hi));
    return r;
}
__device__ __forceinline__ unsigned long long fma2(unsigned long long a,
                                                   unsigned long long b,
                                                   unsigned long long c) {
    unsigned long long d;
    asm("fma.rn.f32x2 %0, %1, %2, %3;" : "=l"(d) : "l"(a), "l"(b), "l"(c));
    return d;
}
__device__ __forceinline__ float2 unp(unsigned long long a) {
    float lo, hi;
    asm("mov.b64 {%0, %1}, %2;" : "=f"(lo), "=f"(hi) : "l"(a));
    return make_float2(lo, hi);
}

// outv = dot(W[row][0:32], unpacked(INP)) ; W rows 32 floats, 16B-aligned
#define ROWDOT(Wsm, row, INP, outv)                                              \
{   const ulonglong2* _wp = reinterpret_cast<const ulonglong2*>((Wsm) + (row) * 32); \
    unsigned long long _a0, _a1, _a2, _a3;                                       \
    ulonglong2 _w0 = _wp[0], _w1 = _wp[1];                                       \
    _a0 = fma2(_w0.x, INP[0], 0ULL);  _a1 = fma2(_w0.y, INP[1], 0ULL);           \
    _a2 = fma2(_w1.x, INP[2], 0ULL);  _a3 = fma2(_w1.y, INP[3], 0ULL);           \
    ulonglong2 _w2 = _wp[2], _w3 = _wp[3];                                       \
    _a0 = fma2(_w2.x, INP[4], _a0);   _a1 = fma2(_w2.y, INP[5], _a1);            \
    _a2 = fma2(_w3.x, INP[6], _a2);   _a3 = fma2(_w3.y, INP[7], _a3);            \
    ulonglong2 _w4 = _wp[4], _w5 = _wp[5];                                       \
    _a0 = fma2(_w4.x, INP[8], _a0);   _a1 = fma2(_w4.y, INP[9], _a1);            \
    _a2 = fma2(_w5.x, INP[10], _a2);  _a3 = fma2(_w5.y, INP[11], _a3);           \
    ulonglong2 _w6 = _wp[6], _w7 = _wp[7];                                       \
    _a0 = fma2(_w6.x, INP[12], _a0);  _a1 = fma2(_w6.y, INP[13], _a1);           \
    _a2 = fma2(_w7.x, INP[14], _a2);  _a3 = fma2(_w7.y, INP[15], _a3);           \
    float2 _u0 = unp(_a0), _u1 = unp(_a1), _u2 = unp(_a2), _u3 = unp(_a3);       \
    (outv) = ((_u0.x + _u0.y) + (_u1.x + _u1.y))                                 \
           + ((_u2.x + _u2.y) + (_u3.x + _u3.y)); }

__global__ __launch_bounds__(256, 1)
void jastrow_kernel(const float* __restrict__ x,
                    const float* __restrict__ W_node, const float* __restrict__ b_node,
                    const float* __restrict__ We1,  const float* __restrict__ be1,
                    const float* __restrict__ We2,  const float* __restrict__ be2,
                    const float* __restrict__ Wv2e, const float* __restrict__ We2v,
                    const float* __restrict__ Wu1,  const float* __restrict__ bu1,
                    const float* __restrict__ Wu2,  const float* __restrict__ bu2,
                    const float* __restrict__ Wn1,  const float* __restrict__ bn1,
                    const float* __restrict__ Wn2,  const float* __restrict__ bn2,
                    const float* __restrict__ Wf1,  const float* __restrict__ bf1,
                    const float* __restrict__ Wf2,  const float* __restrict__ bf2,
                    const float* __restrict__ Wf3,  const float* __restrict__ bf3,
                    float* __restrict__ out)
{
    __shared__ float sx[96];
    __shared__ float shv[32 * 33];     // h_v (pre-update)
    __shared__ float sp [32 * 33];     // p, later m_v
    __shared__ float sq [32 * 33];     // q_i, later a1
    __shared__ float ssj[32 * 33];     // s_j, later h_v_new
    __shared__ float srs[32 * 33];     // row sums of h_e_new
    __shared__ __align__(16) float sWe1 [32 * 8];   // [h][0..4]=We1 row, [5]=be1
    __shared__ __align__(16) float sWe2 [32 * 32];  // row-major [c][k]
    __shared__ __align__(16) float sWu1a[32 * 32];  // [h][k] (h_e part of Wu1)
    __shared__ __align__(16) float sWu2 [32 * 32];  // [c][k]
    __shared__ float sbe2[32], sbu2[32];
    __shared__ float spair[32];
    __shared__ float sred[3];
    __shared__ float sfin[132], sf1[64], sf2[64];
    extern __shared__ float dynsmem[];              // per-warp transpose scratch 8*32*33

    const int tid  = threadIdx.x;
    const int lane = tid & 31;
    const int w    = tid >> 5;
    const int b    = blockIdx.x;

    // ---- stage inputs & weights ----
    if (tid < 96) sx[tid] = x[b * 96 + tid];
    if (tid < 32) { spair[tid] = 0.0f; sbe2[tid] = be2[tid]; sbu2[tid] = bu2[tid]; }
    if (tid < 3)  sred[tid] = 0.0f;
    for (int k = tid; k < 256; k += 256) {
        int h = k >> 3, c = k & 7;
        float v = 0.0f;
        if (c < 5)       v = We1[h * 5 + c];
        else if (c == 5) v = be1[h];
        sWe1[k] = v;
    }
    for (int k = tid; k < 1024; k += 256) {
        sWe2 [k] = We2[k];
        sWu1a[k] = Wu1[(k >> 5) * 96 + (k & 31)];
        sWu2 [k] = Wu2[k];
    }
    __syncthreads();

    // ---- node phases: lane = node index i, (warp,iter) = channel ----
    #pragma unroll
    for (int it = 0; it < 4; it++) {
        int ch = w + it * 8;
        int i  = lane;
        float sf = (i >= 16) ? 1.0f : 0.0f;
        float a = b_node[ch]
                + W_node[ch * 4 + 0] * sx[i * 3 + 0]
                + W_node[ch * 4 + 1] * sx[i * 3 + 1]
                + W_node[ch * 4 + 2] * sx[i * 3 + 2]
                + W_node[ch * 4 + 3] * sf;
        shv[i * 33 + ch] = a;
    }
    __syncthreads();

    // p = h_v @ Wv2e^T
    #pragma unroll
    for (int it = 0; it < 4; it++) {
        int m = w + it * 8;
        int i = lane;
        float a0 = 0.f, a1 = 0.f;
        #pragma unroll
        for (int h = 0; h < 32; h += 2) {
            a0 = fmaf(Wv2e[m * 32 + h + 0], shv[i * 33 + h + 0], a0);
            a1 = fmaf(Wv2e[m * 32 + h + 1], shv[i * 33 + h + 1], a1);
        }
        sp[i * 33 + m] = a0 + a1;
    }
    __syncthreads();

    // q_i = Wu1[:,32:64]@p_i + bu1 ; s_j = Wu1[:,64:96]@p_j
    #pragma unroll
    for (int it = 0; it < 4; it++) {
        int h = w + it * 8;
        int i = lane;
        float aq = bu1[h], as = 0.f;
        #pragma unroll
        for (int m = 0; m < 32; m++) {
            float pv = sp[i * 33 + m];
            aq = fmaf(Wu1[h * 96 + 32 + m], pv, aq);
            as = fmaf(Wu1[h * 96 + 64 + m], pv, as);
        }
        sq [i * 33 + h] = aq;
        ssj[i * 33 + h] = as;
    }
    __syncthreads();

    // ---- edge loop: lane = j; warp w owns rows i = 4w..4w+3 ----
    const int j = lane;
    const float xj0 = sx[j * 3 + 0], xj1 = sx[j * 3 + 1], xj2 = sx[j * 3 + 2];
    const float4* sWe1_4 = reinterpret_cast<const float4*>(sWe1);
    float* scr = &dynsmem[w * 32 * 33];

    float pacc[32];
    #pragma unroll
    for (int c = 0; c < 32; c++) pacc[c] = 0.0f;

    #pragma unroll 1
    for (int ii = 0; ii < 4; ii++) {
        const int i = w * 4 + ii;
        const float fr0 = sx[i * 3 + 0] - xj0;
        const float fr1 = sx[i * 3 + 1] - xj1;
        const float fr2 = sx[i * 3 + 2] - xj2;
        const float rr2 = fmaf(fr0, fr0, fmaf(fr1, fr1, fr2 * fr2));
        const float tpl = rr2 + 1e-12f;
        const float rr1 = tpl * __frsqrt_rn(tpl);
        const float mr  = (j != i) ? 1.0f : 0.0f;
        const float mp  = (i < j)  ? 1.0f : 0.0f;

        // stage 1: Ap = packed silu(We1 @ [r, |r|, r^2] + be1)
        unsigned long long Ap[16];
        #pragma unroll
        for (int h = 0; h < 32; h += 2) {
            float4 wa0 = sWe1_4[h * 2 + 0], wa1 = sWe1_4[h * 2 + 1];
            float a0 = wa1.y;
            a0 = fmaf(wa0.x, fr0, a0); a0 = fmaf(wa0.y, fr1, a0);
            a0 = fmaf(wa0.z, fr2, a0); a0 = fmaf(wa0.w, rr1, a0);
            a0 = fmaf(wa1.x, rr2, a0);
            float4 wb0 = sWe1_4[h * 2 + 2], wb1 = sWe1_4[h * 2 + 3];
            float a1 = wb1.y;
            a1 = fmaf(wb0.x, fr0, a1); a1 = fmaf(wb0.y, fr1, a1);
            a1 = fmaf(wb0.z, fr2, a1); a1 = fmaf(wb0.w, rr1, a1);
            a1 = fmaf(wb1.x, rr2, a1);
            Ap[h / 2] = pack2(silu_f(a0), silu_f(a1));
        }

        // stage 2: Bp = packed h_e = We2 @ t + be2
        unsigned long long Bp[16];
        #pragma unroll
        for (int c = 0; c < 32; c += 2) {
            float he0, he1;
            ROWDOT(sWe2, c,     Ap, he0);
            ROWDOT(sWe2, c + 1, Ap, he1);
            Bp[c / 2] = pack2(he0 + sbe2[c], he1 + sbe2[c + 1]);
        }

        // stage 3: Ap = packed silu(q_i + s_j + Wu1a @ h_e)
        #pragma unroll
        for (int h = 0; h < 32; h += 2) {
            float t0, t1;
            ROWDOT(sWu1a, h,     Bp, t0);
            ROWDOT(sWu1a, h + 1, Bp, t1);
            t0 += sq[i * 33 + h]     + ssj[j * 33 + h];
            t1 += sq[i * 33 + h + 1] + ssj[j * 33 + h + 1];
            Ap[h / 2] = pack2(silu_f(t0), silu_f(t1));
        }

        // stage 4: h_e_new per channel; store masked value straight to scratch,
        // fold pair contribution into pacc.  (No racc array -> lower reg pressure.)
        __syncwarp();
        #pragma unroll
        for (int c = 0; c < 32; c += 2) {
            float hn0, hn1;
            ROWDOT(sWu2, c,     Ap, hn0);
            ROWDOT(sWu2, c + 1, Ap, hn1);
            hn0 += sbu2[c]; hn1 += sbu2[c + 1];
            float2 he = unp(Bp[c / 2]);
            scr[j * 33 + c]     = mr * hn0;
            scr[j * 33 + c + 1] = mr * hn1;
            pacc[c]     = fmaf(mp, hn0 + he.x, pacc[c]);
            pacc[c + 1] = fmaf(mp, hn1 + he.y, pacc[c + 1]);
        }
        __syncwarp();

        // transpose-reduce over lanes -> srs[i][*]
        {
            float s0 = 0.f, s1 = 0.f, s2 = 0.f, s3 = 0.f;
            #pragma unroll
            for (int jj = 0; jj < 32; jj += 4) {
                s0 += scr[(jj + 0) * 33 + lane];
                s1 += scr[(jj + 1) * 33 + lane];
                s2 += scr[(jj + 2) * 33 + lane];
                s3 += scr[(jj + 3) * 33 + lane];
            }
            srs[i * 33 + lane] = (s0 + s1) + (s2 + s3);
        }
    }

    // pair-sum: transpose-reduce pacc, one atomic per lane per warp
    __syncwarp();
    #pragma unroll
    for (int c = 0; c < 32; c++) scr[j * 33 + c] = pacc[c];
    __syncwarp();
    {
        float s0 = 0.f, s1 = 0.f, s2 = 0.f, s3 = 0.f;
        #pragma unroll
        for (int jj = 0; jj < 32; jj += 4) {
            s0 += scr[(jj + 0) * 33 + lane];
            s1 += scr[(jj + 1) * 33 + lane];
            s2 += scr[(jj + 2) * 33 + lane];
            s3 += scr[(jj + 3) * 33 + lane];
        }
        atomicAdd(&spair[lane], (s0 + s1) + (s2 + s3));
    }
    __syncthreads();

    // ---- m_v = We2v @ rowsum  (reuse sp) ----
    #pragma unroll
    for (int it = 0; it < 4; it++) {
        int h = w + it * 8;
        int i = lane;
        float a0 = 0.f, a1 = 0.f;
        #pragma unroll
        for (int c = 0; c < 32; c += 2) {
            a0 = fmaf(We2v[h * 32 + c + 0], srs[i * 33 + c + 0], a0);
            a1 = fmaf(We2v[h * 32 + c + 1], srs[i * 33 + c + 1], a1);
        }
        sp[i * 33 + h] = a0 + a1;
    }
    __syncthreads();

    // ---- a1 = silu(Wn1 @ [h_v, m_v] + bn1)  (reuse sq) ----
    #pragma unroll
    for (int it = 0; it < 4; it++) {
        int h = w + it * 8;
        int i = lane;
        float a = bn1[h];
        #pragma unroll
        for (int k = 0; k < 32; k++) a = fmaf(Wn1[h * 64 + k],      shv[i * 33 + k], a);
        #pragma unroll
        for (int k = 0; k < 32; k++) a = fmaf(Wn1[h * 64 + 32 + k], sp [i * 33 + k], a);
        sq[i * 33 + h] = silu_f(a);
    }
    __syncthreads();

    // ---- h_v_new = h_v + Wn2 @ a1 + bn2  (reuse ssj) ----
    #pragma unroll
    for (int it = 0; it < 4; it++) {
        int h = w + it * 8;
        int i = lane;
        float a = shv[i * 33 + h] + bn2[h];
        #pragma unroll
        for (int c = 0; c < 32; c++) a = fmaf(Wn2[h * 32 + c], sq[i * 33 + c], a);
        ssj[i * 33 + h] = a;
    }

    // ---- pairwise scalars: r2_sum, s1_sum, cusp ----
    float r2_l = 0.0f, s1_l = 0.0f, cusp_l = 0.0f;
    if (tid < 96) r2_l = sx[tid] * sx[tid];
    for (int idx = tid; idx < 496; idx += 256) {
        int rem = idx, pi = 0, cnt = 31;
        while (rem >= cnt) { rem -= cnt; pi++; cnt--; }
        int pj = pi + 1 + rem;
        float d0 = sx[pi * 3 + 0] - sx[pj * 3 + 0];
        float d1 = sx[pi * 3 + 1] - sx[pj * 3 + 1];
        float d2 = sx[pi * 3 + 2] - sx[pj * 3 + 2];
        float dd = fmaf(d0, d0, fmaf(d1, d1, d2 * d2));
        s1_l += log1pf((dd + 1e-8f) * 25.0f);
        float rc = sqrtf(dd + 1e-30f);
        bool same = (pi < 16) == (pj < 16);
        float gamma = same ? 0.25f : 0.5f;
        cusp_l += gamma * rc * __expf(-rc);
    }
    #pragma unroll
    for (int s = 16; s > 0; s >>= 1) {
        r2_l   += __shfl_xor_sync(0xffffffffu, r2_l,   s);
        s1_l   += __shfl_xor_sync(0xffffffffu, s1_l,   s);
        cusp_l += __shfl_xor_sync(0xffffffffu, cusp_l, s);
    }
    if (lane == 0) {
        atomicAdd(&sred[0], r2_l);
        atomicAdd(&sred[1], s1_l);
        atomicAdd(&sred[2], cusp_l);
    }
    __syncthreads();

    // ---- assemble f_in (130) ----
    if (tid < 32) {
        float hs = 0.0f;
        #pragma unroll
        for (int i2 = 0; i2 < 32; i2++) hs += ssj[i2 * 33 + tid];
        sfin[tid]      = hs;
        sfin[32 + tid] = hs * (1.0f / 32.0f);
        float ps = spair[tid];
        sfin[64 + tid] = ps;
        sfin[96 + tid] = ps * (1.0f / 496.0f);
    }
    if (tid == 0) {
        sfin[128] = sred[0] * (1.0f / 96.0f);
        sfin[129] = sred[1] * (1.0f / 496.0f);
        sfin[130] = 0.0f;  sfin[131] = 0.0f;
    }
    __syncthreads();

    // ---- readout: 130 -> 64 -> 64 -> 1 ----
    #pragma unroll 1
    for (int oo = 0; oo < 8; oo++) {
        int o = w * 8 + oo;
        float a = 0.0f;
        a = fmaf(Wf1[o * 130 + lane],      sfin[lane],      a);
        a = fmaf(Wf1[o * 130 + lane + 32], sfin[lane + 32], a);
        a = fmaf(Wf1[o * 130 + lane + 64], sfin[lane + 64], a);
        a = fmaf(Wf1[o * 130 + lane + 96], sfin[lane + 96], a);
        if (lane < 2) a = fmaf(Wf1[o * 130 + lane + 128], sfin[lane + 128], a);
        #pragma unroll
        for (int s = 16; s > 0; s >>= 1) a += __shfl_xor_sync(0xffffffffu, a, s);
        if (lane == 0) sf1[o] = silu_f(a + bf1[o]);
    }
    __syncthreads();

    #pragma unroll 1
    for (int oo = 0; oo < 8; oo++) {
        int o = w * 8 + oo;
        float a = fmaf(Wf2[o * 64 + lane],      sf1[lane],      0.0f);
        a       = fmaf(Wf2[o * 64 + lane + 32], sf1[lane + 32], a);
        #pragma unroll
        for (int s = 16; s > 0; s >>= 1) a += __shfl_xor_sync(0xffffffffu, a, s);
        if (lane == 0) sf2[o] = silu_f(a + bf2[o]);
    }
    __syncthreads();

    if (w == 0) {
        float a = fmaf(Wf3[lane],      sf2[lane],      0.0f);
        a       = fmaf(Wf3[lane + 32], sf2[lane + 32], a);
        #pragma unroll
        for (int s = 16; s > 0; s >>= 1) a += __shfl_xor_sync(0xffffffffu, a, s);
        if (lane == 0) out[b] = a + bf3[0] + sred[2];
    }
}

extern "C" void kernel_launch(void* const* d_in, const int* in_sizes, int n_in,
                              void* d_out, int out_size)
{
    const float* x      = (const float*)d_in[0];
    const float* W_node = (const float*)d_in[1];
    const float* b_node = (const float*)d_in[2];
    const float* We1    = (const float*)d_in[3];
    const float* be1    = (const float*)d_in[4];
    const float* We2    = (const float*)d_in[5];
    const float* be2    = (const float*)d_in[6];
    const float* Wv2e   = (const float*)d_in[7];
    const float* We2v   = (const float*)d_in[8];
    const float* Wu1    = (const float*)d_in[9];
    const float* bu1    = (const float*)d_in[10];
    const float* Wu2    = (const float*)d_in[11];
    const float* bu2    = (const float*)d_in[12];
    const float* Wn1    = (const float*)d_in[13];
    const float* bn1    = (const float*)d_in[14];
    const float* Wn2    = (const float*)d_in[15];
    const float* bn2    = (const float*)d_in[16];
    const float* Wf1    = (const float*)d_in[17];
    const float* bf1    = (const float*)d_in[18];
    const float* Wf2    = (const float*)d_in[19];
    const float* bf2    = (const float*)d_in[20];
    const float* Wf3    = (const float*)d_in[21];
    const float* bf3    = (const float*)d_in[22];

    const int dyn_smem = 8 * 32 * 33 * (int)sizeof(float);   // 33792 B
    static bool attr_set = false;
    if (!attr_set) {
        cudaFuncSetAttribute(jastrow_kernel,
                             cudaFuncAttributeMaxDynamicSharedMemorySize, dyn_smem);
        attr_set = true;
    }

    int B = in_sizes[0] / 96;   // (B, 32, 3)
    jastrow_kernel<<<B, 256, dyn_smem>>>(x, W_node, b_node, We1, be1, We2, be2,
                                         Wv2e, We2v, Wu1, bu1, Wu2, bu2,
                                         Wn1, bn1, Wn2, bn2,
                                         Wf1, bf1, Wf2, bf2, Wf3, bf3,
                                         (float*)d_out);
}

// round 8
// speedup vs baseline: 2.0928x; 1.3950x over previous
#include <cuda_runtime.h>
#include <cstdint>

// CTNNBackflowStyleJastrow: B=1024, N=32, D=3, H=M=32, RH=64
// One CTA (256 threads = 8 warps) per batch element.
// Edge loop: per warp-row i, all 3 heavy 32x32x32 stages run as tf32 mma.sync
// GEMMs with register-resident weight B-fragments. Stage chaining through
// per-warp smem buffers (stride 36 -> conflict-free A-fragment loads).

__device__ __forceinline__ float silu_f(float x) {
    return __fdividef(x, 1.0f + __expf(-x));
}
__device__ __forceinline__ uint32_t f2tf(float f) {
    uint32_t r; asm("cvt.rna.tf32.f32 %0, %1;" : "=r"(r) : "f"(f)); return r;
}
__device__ __forceinline__ float tfbits(float f) {   // tf32-rounded value as float
    return __uint_as_float(f2tf(f));
}
__device__ __forceinline__ void mma_tf32(float& d0, float& d1, float& d2, float& d3,
                                         uint32_t a0, uint32_t a1, uint32_t a2, uint32_t a3,
                                         uint32_t b0, uint32_t b1) {
    asm volatile("mma.sync.aligned.m16n8k8.row.col.f32.tf32.tf32.f32 "
                 "{%0,%1,%2,%3}, {%4,%5,%6,%7}, {%8,%9}, {%0,%1,%2,%3};"
                 : "+f"(d0), "+f"(d1), "+f"(d2), "+f"(d3)
                 : "r"(a0), "r"(a1), "r"(a2), "r"(a3), "r"(b0), "r"(b1));
}

#define ST 36   // stride of per-warp T/HE buffers (conflict-free A-frag loads)

__global__ __launch_bounds__(256, 1)
void jastrow_kernel(const float* __restrict__ x,
                    const float* __restrict__ W_node, const float* __restrict__ b_node,
                    const float* __restrict__ We1,  const float* __restrict__ be1,
                    const float* __restrict__ We2,  const float* __restrict__ be2,
                    const float* __restrict__ Wv2e, const float* __restrict__ We2v,
                    const float* __restrict__ Wu1,  const float* __restrict__ bu1,
                    const float* __restrict__ Wu2,  const float* __restrict__ bu2,
                    const float* __restrict__ Wn1,  const float* __restrict__ bn1,
                    const float* __restrict__ Wn2,  const float* __restrict__ bn2,
                    const float* __restrict__ Wf1,  const float* __restrict__ bf1,
                    const float* __restrict__ Wf2,  const float* __restrict__ bf2,
                    const float* __restrict__ Wf3,  const float* __restrict__ bf3,
                    float* __restrict__ out)
{
    __shared__ float sx[96];
    __shared__ float shv[32 * 33];                 // h_v (pre-update), stride 33
    __shared__ float sp [32 * 33];                 // p, later m_v, stride 33
    __shared__ __align__(8) float sq [32 * 34];    // q_i, later a1   (stride 34: f32x2 loads)
    __shared__ __align__(8) float ssj[32 * 34];    // s_j, later h_v_new
    __shared__ float srs[32 * 33];                 // row sums of h_e_new
    __shared__ __align__(8) float sbe1[32], sbe2[32], sbu2[32];
    __shared__ float spair[32];
    __shared__ float sred[3];
    __shared__ float sfin[132], sf1[64], sf2[64];
    extern __shared__ __align__(16) float dynsmem[];   // per warp: T[32*36] + HE[32*36]

    const int tid  = threadIdx.x;
    const int lane = tid & 31;
    const int w    = tid >> 5;
    const int b    = blockIdx.x;
    const int gid  = lane >> 2;       // mma group id (0..7)
    const int tig  = lane & 3;        // thread in group (0..3)

    // ---- register-resident tf32 weight B-fragments (loaded once) ----
    // B(k,n) = W[n][k]; b0: (k=tig, n=gid), b1: (k=tig+4, n=gid) per (nt,kt) tile.
    uint32_t bWe1[8], bWe2[32], bWu1[32], bWu2[32];
    #pragma unroll
    for (int nt = 0; nt < 4; nt++) {
        int n = 8 * nt + gid;
        bWe1[nt * 2 + 0] = f2tf(We1[n * 5 + tig]);
        bWe1[nt * 2 + 1] = (tig == 0) ? f2tf(We1[n * 5 + 4]) : 0u;
        #pragma unroll
        for (int kt = 0; kt < 4; kt++) {
            int k = 8 * kt + tig;
            bWe2[nt * 8 + kt * 2 + 0] = f2tf(We2[n * 32 + k]);
            bWe2[nt * 8 + kt * 2 + 1] = f2tf(We2[n * 32 + k + 4]);
            bWu1[nt * 8 + kt * 2 + 0] = f2tf(Wu1[n * 96 + k]);
            bWu1[nt * 8 + kt * 2 + 1] = f2tf(Wu1[n * 96 + k + 4]);
            bWu2[nt * 8 + kt * 2 + 0] = f2tf(Wu2[n * 32 + k]);
            bWu2[nt * 8 + kt * 2 + 1] = f2tf(Wu2[n * 32 + k + 4]);
        }
    }

    // ---- stage inputs & biases ----
    if (tid < 96) sx[tid] = x[b * 96 + tid];
    if (tid < 32) {
        spair[tid] = 0.0f;
        sbe1[tid] = be1[tid]; sbe2[tid] = be2[tid]; sbu2[tid] = bu2[tid];
    }
    if (tid < 3)  sred[tid] = 0.0f;
    __syncthreads();

    // ---- node phases: lane = node index i, (warp,iter) = channel ----
    #pragma unroll
    for (int it = 0; it < 4; it++) {
        int ch = w + it * 8;
        int i  = lane;
        float sf = (i >= 16) ? 1.0f : 0.0f;
        float a = b_node[ch]
                + W_node[ch * 4 + 0] * sx[i * 3 + 0]
                + W_node[ch * 4 + 1] * sx[i * 3 + 1]
                + W_node[ch * 4 + 2] * sx[i * 3 + 2]
                + W_node[ch * 4 + 3] * sf;
        shv[i * 33 + ch] = a;
    }
    __syncthreads();

    // p = h_v @ Wv2e^T
    #pragma unroll
    for (int it = 0; it < 4; it++) {
        int m = w + it * 8;
        int i = lane;
        float a0 = 0.f, a1 = 0.f;
        #pragma unroll
        for (int h = 0; h < 32; h += 2) {
            a0 = fmaf(Wv2e[m * 32 + h + 0], shv[i * 33 + h + 0], a0);
            a1 = fmaf(Wv2e[m * 32 + h + 1], shv[i * 33 + h + 1], a1);
        }
        sp[i * 33 + m] = a0 + a1;
    }
    __syncthreads();

    // q_i = Wu1[:,32:64]@p_i + bu1 ; s_j = Wu1[:,64:96]@p_j   (stride 34)
    #pragma unroll
    for (int it = 0; it < 4; it++) {
        int h = w + it * 8;
        int i = lane;
        float aq = bu1[h], as = 0.f;
        #pragma unroll
        for (int m = 0; m < 32; m++) {
            float pv = sp[i * 33 + m];
            aq = fmaf(Wu1[h * 96 + 32 + m], pv, aq);
            as = fmaf(Wu1[h * 96 + 64 + m], pv, as);
        }
        sq [i * 34 + h] = aq;
        ssj[i * 34 + h] = as;
    }
    __syncthreads();

    // ---- edge loop: warp w owns rows i = 4w..4w+3; GEMM per stage ----
    float* Tb = dynsmem + w * (2 * 32 * ST);
    float* HE = Tb + 32 * ST;
    float* F  = HE;                    // stage-1 feature scratch aliases HE (stride 12)

    const float xj0 = sx[lane * 3 + 0], xj1 = sx[lane * 3 + 1], xj2 = sx[lane * 3 + 2];
    float pacc = 0.0f;

    #pragma unroll 1
    for (int ii = 0; ii < 4; ii++) {
        const int i = w * 4 + ii;

        // features (lane = edge j): F[j] = tf32([r0,r1,r2,|r|,r^2,0,0,0])
        {
            float fr0 = sx[i * 3 + 0] - xj0;
            float fr1 = sx[i * 3 + 1] - xj1;
            float fr2 = sx[i * 3 + 2] - xj2;
            float rr2 = fmaf(fr0, fr0, fmaf(fr1, fr1, fr2 * fr2));
            float tpl = rr2 + 1e-12f;
            float rr1 = tpl * __frsqrt_rn(tpl);
            __syncwarp();   // prior iter's reduction reads of HE done
            *reinterpret_cast<float4*>(&F[lane * 12]) =
                make_float4(tfbits(fr0), tfbits(fr1), tfbits(fr2), tfbits(rr1));
            *reinterpret_cast<float4*>(&F[lane * 12 + 4]) =
                make_float4(tfbits(rr2), 0.0f, 0.0f, 0.0f);
            __syncwarp();
        }

        // stage 1: T = silu(F @ We1^T + be1)   (K=8, 1 K-tile)
        #pragma unroll
        for (int mt = 0; mt < 2; mt++) {
            uint32_t A0 = __float_as_uint(F[(16 * mt + gid) * 12 + tig]);
            uint32_t A1 = __float_as_uint(F[(16 * mt + gid + 8) * 12 + tig]);
            uint32_t A2 = __float_as_uint(F[(16 * mt + gid) * 12 + tig + 4]);
            uint32_t A3 = __float_as_uint(F[(16 * mt + gid + 8) * 12 + tig + 4]);
            #pragma unroll
            for (int nt = 0; nt < 4; nt++) {
                int col = 8 * nt + 2 * tig;
                float2 bb = *reinterpret_cast<const float2*>(&sbe1[col]);
                float d0 = bb.x, d1 = bb.y, d2 = bb.x, d3 = bb.y;
                mma_tf32(d0, d1, d2, d3, A0, A1, A2, A3, bWe1[nt * 2], bWe1[nt * 2 + 1]);
                int r0 = (16 * mt + gid) * ST + col;
                *reinterpret_cast<float2*>(&Tb[r0]) =
                    make_float2(tfbits(silu_f(d0)), tfbits(silu_f(d1)));
                *reinterpret_cast<float2*>(&Tb[r0 + 8 * ST]) =
                    make_float2(tfbits(silu_f(d2)), tfbits(silu_f(d3)));
            }
        }
        __syncwarp();

        // stage 2: HE = T @ We2^T + be2
        #pragma unroll
        for (int mt = 0; mt < 2; mt++) {
            uint32_t Ar[16];
            #pragma unroll
            for (int kt = 0; kt < 4; kt++) {
                const float* p0 = &Tb[(16 * mt + gid) * ST + 8 * kt + tig];
                const float* p1 = &Tb[(16 * mt + gid + 8) * ST + 8 * kt + tig];
                Ar[4 * kt + 0] = __float_as_uint(p0[0]);
                Ar[4 * kt + 1] = __float_as_uint(p1[0]);
                Ar[4 * kt + 2] = __float_as_uint(p0[4]);
                Ar[4 * kt + 3] = __float_as_uint(p1[4]);
            }
            #pragma unroll
            for (int nt = 0; nt < 4; nt++) {
                int col = 8 * nt + 2 * tig;
                float2 bb = *reinterpret_cast<const float2*>(&sbe2[col]);
                float d0 = bb.x, d1 = bb.y, d2 = bb.x, d3 = bb.y;
                #pragma unroll
                for (int kt = 0; kt < 4; kt++)
                    mma_tf32(d0, d1, d2, d3,
                             Ar[4 * kt + 0], Ar[4 * kt + 1], Ar[4 * kt + 2], Ar[4 * kt + 3],
                             bWe2[nt * 8 + kt * 2], bWe2[nt * 8 + kt * 2 + 1]);
                int r0 = (16 * mt + gid) * ST + col;
                *reinterpret_cast<float2*>(&HE[r0]) = make_float2(tfbits(d0), tfbits(d1));
                *reinterpret_cast<float2*>(&HE[r0 + 8 * ST]) = make_float2(tfbits(d2), tfbits(d3));
            }
        }
        __syncwarp();

        // stage 3: T = silu(HE @ Wu1a^T + q_i[col] + s_j[row][col])
        #pragma unroll
        for (int mt = 0; mt < 2; mt++) {
            uint32_t Ar[16];
            #pragma unroll
            for (int kt = 0; kt < 4; kt++) {
                const float* p0 = &HE[(16 * mt + gid) * ST + 8 * kt + tig];
                const float* p1 = &HE[(16 * mt + gid + 8) * ST + 8 * kt + tig];
                Ar[4 * kt + 0] = __float_as_uint(p0[0]);
                Ar[4 * kt + 1] = __float_as_uint(p1[0]);
                Ar[4 * kt + 2] = __float_as_uint(p0[4]);
                Ar[4 * kt + 3] = __float_as_uint(p1[4]);
            }
            #pragma unroll
            for (int nt = 0; nt < 4; nt++) {
                int col = 8 * nt + 2 * tig;
                float2 qv = *reinterpret_cast<const float2*>(&sq[i * 34 + col]);
                float2 s0 = *reinterpret_cast<const float2*>(&ssj[(16 * mt + gid) * 34 + col]);
                float2 s1 = *reinterpret_cast<const float2*>(&ssj[(16 * mt + gid + 8) * 34 + col]);
                float d0 = qv.x + s0.x, d1 = qv.y + s0.y;
                float d2 = qv.x + s1.x, d3 = qv.y + s1.y;
                #pragma unroll
                for (int kt = 0; kt < 4; kt++)
                    mma_tf32(d0, d1, d2, d3,
                             Ar[4 * kt + 0], Ar[4 * kt + 1], Ar[4 * kt + 2], Ar[4 * kt + 3],
                             bWu1[nt * 8 + kt * 2], bWu1[nt * 8 + kt * 2 + 1]);
                int r0 = (16 * mt + gid) * ST + col;
                *reinterpret_cast<float2*>(&Tb[r0]) =
                    make_float2(tfbits(silu_f(d0)), tfbits(silu_f(d1)));
                *reinterpret_cast<float2*>(&Tb[r0 + 8 * ST]) =
                    make_float2(tfbits(silu_f(d2)), tfbits(silu_f(d3)));
            }
        }
        __syncwarp();

        // stage 4: T = T @ Wu2^T + bu2   (in-place safe: A rows of a tile are
        // loaded before that tile's stores; mt=1 reads rows 16..31, mt=0 wrote 0..15)
        #pragma unroll
        for (int mt = 0; mt < 2; mt++) {
            uint32_t Ar[16];
            #pragma unroll
            for (int kt = 0; kt < 4; kt++) {
                const float* p0 = &Tb[(16 * mt + gid) * ST + 8 * kt + tig];
                const float* p1 = &Tb[(16 * mt + gid + 8) * ST + 8 * kt + tig];
                Ar[4 * kt + 0] = __float_as_uint(p0[0]);
                Ar[4 * kt + 1] = __float_as_uint(p1[0]);
                Ar[4 * kt + 2] = __float_as_uint(p0[4]);
                Ar[4 * kt + 3] = __float_as_uint(p1[4]);
            }
            __syncwarp();
            #pragma unroll
            for (int nt = 0; nt < 4; nt++) {
                int col = 8 * nt + 2 * tig;
                float2 bb = *reinterpret_cast<const float2*>(&sbu2[col]);
                float d0 = bb.x, d1 = bb.y, d2 = bb.x, d3 = bb.y;
                #pragma unroll
                for (int kt = 0; kt < 4; kt++)
                    mma_tf32(d0, d1, d2, d3,
                             Ar[4 * kt + 0], Ar[4 * kt + 1], Ar[4 * kt + 2], Ar[4 * kt + 3],
                             bWu2[nt * 8 + kt * 2], bWu2[nt * 8 + kt * 2 + 1]);
                int r0 = (16 * mt + gid) * ST + col;
                *reinterpret_cast<float2*>(&Tb[r0]) = make_float2(d0, d1);
                *reinterpret_cast<float2*>(&Tb[r0 + 8 * ST]) = make_float2(d2, d3);
            }
        }
        __syncwarp();

        // reduction: lane = channel c
        {
            float rsum = 0.0f, psum = 0.0f;
            #pragma unroll
            for (int jj = 0; jj < 32; jj++) {
                float hn = Tb[jj * ST + lane];
                float he = HE[jj * ST + lane];
                rsum += hn;
                float mk = (jj > i) ? 1.0f : 0.0f;
                psum = fmaf(mk, hn + he, psum);
            }
            rsum -= Tb[i * ST + lane];
            srs[i * 33 + lane] = rsum;
            pacc += psum;
        }
    }
    atomicAdd(&spair[lane], pacc);
    __syncthreads();

    // ---- m_v = We2v @ rowsum  (reuse sp) ----
    #pragma unroll
    for (int it = 0; it < 4; it++) {
        int h = w + it * 8;
        int i = lane;
        float a0 = 0.f, a1 = 0.f;
        #pragma unroll
        for (int c = 0; c < 32; c += 2) {
            a0 = fmaf(We2v[h * 32 + c + 0], srs[i * 33 + c + 0], a0);
            a1 = fmaf(We2v[h * 32 + c + 1], srs[i * 33 + c + 1], a1);
        }
        sp[i * 33 + h] = a0 + a1;
    }
    __syncthreads();

    // ---- a1 = silu(Wn1 @ [h_v, m_v] + bn1)  (reuse sq) ----
    #pragma unroll
    for (int it = 0; it < 4; it++) {
        int h = w + it * 8;
        int i = lane;
        float a = bn1[h];
        #pragma unroll
        for (int k = 0; k < 32; k++) a = fmaf(Wn1[h * 64 + k],      shv[i * 33 + k], a);
        #pragma unroll
        for (int k = 0; k < 32; k++) a = fmaf(Wn1[h * 64 + 32 + k], sp [i * 33 + k], a);
        sq[i * 34 + h] = silu_f(a);
    }
    __syncthreads();

    // ---- h_v_new = h_v + Wn2 @ a1 + bn2  (reuse ssj) ----
    #pragma unroll
    for (int it = 0; it < 4; it++) {
        int h = w + it * 8;
        int i = lane;
        float a = shv[i * 33 + h] + bn2[h];
        #pragma unroll
        for (int c = 0; c < 32; c++) a = fmaf(Wn2[h * 32 + c], sq[i * 34 + c], a);
        ssj[i * 34 + h] = a;
    }

    // ---- pairwise scalars: r2_sum, s1_sum, cusp ----
    float r2_l = 0.0f, s1_l = 0.0f, cusp_l = 0.0f;
    if (tid < 96) r2_l = sx[tid] * sx[tid];
    for (int idx = tid; idx < 496; idx += 256) {
        int rem = idx, pi = 0, cnt = 31;
        while (rem >= cnt) { rem -= cnt; pi++; cnt--; }
        int pj = pi + 1 + rem;
        float d0 = sx[pi * 3 + 0] - sx[pj * 3 + 0];
        float d1 = sx[pi * 3 + 1] - sx[pj * 3 + 1];
        float d2 = sx[pi * 3 + 2] - sx[pj * 3 + 2];
        float dd = fmaf(d0, d0, fmaf(d1, d1, d2 * d2));
        s1_l += log1pf((dd + 1e-8f) * 25.0f);
        float rc = sqrtf(dd + 1e-30f);
        bool same = (pi < 16) == (pj < 16);
        float gamma = same ? 0.25f : 0.5f;
        cusp_l += gamma * rc * __expf(-rc);
    }
    #pragma unroll
    for (int s = 16; s > 0; s >>= 1) {
        r2_l   += __shfl_xor_sync(0xffffffffu, r2_l,   s);
        s1_l   += __shfl_xor_sync(0xffffffffu, s1_l,   s);
        cusp_l += __shfl_xor_sync(0xffffffffu, cusp_l, s);
    }
    if (lane == 0) {
        atomicAdd(&sred[0], r2_l);
        atomicAdd(&sred[1], s1_l);
        atomicAdd(&sred[2], cusp_l);
    }
    __syncthreads();

    // ---- assemble f_in (130) ----
    if (tid < 32) {
        float hs = 0.0f;
        #pragma unroll
        for (int i2 = 0; i2 < 32; i2++) hs += ssj[i2 * 34 + tid];
        sfin[tid]      = hs;
        sfin[32 + tid] = hs * (1.0f / 32.0f);
        float ps = spair[tid];
        sfin[64 + tid] = ps;
        sfin[96 + tid] = ps * (1.0f / 496.0f);
    }
    if (tid == 0) {
        sfin[128] = sred[0] * (1.0f / 96.0f);
        sfin[129] = sred[1] * (1.0f / 496.0f);
        sfin[130] = 0.0f;  sfin[131] = 0.0f;
    }
    __syncthreads();

    // ---- readout: 130 -> 64 -> 64 -> 1 ----
    #pragma unroll 1
    for (int oo = 0; oo < 8; oo++) {
        int o = w * 8 + oo;
        float a = 0.0f;
        a = fmaf(Wf1[o * 130 + lane],      sfin[lane],      a);
        a = fmaf(Wf1[o * 130 + lane + 32], sfin[lane + 32], a);
        a = fmaf(Wf1[o * 130 + lane + 64], sfin[lane + 64], a);
        a = fmaf(Wf1[o * 130 + lane + 96], sfin[lane + 96], a);
        if (lane < 2) a = fmaf(Wf1[o * 130 + lane + 128], sfin[lane + 128], a);
        #pragma unroll
        for (int s = 16; s > 0; s >>= 1) a += __shfl_xor_sync(0xffffffffu, a, s);
        if (lane == 0) sf1[o] = silu_f(a + bf1[o]);
    }
    __syncthreads();

    #pragma unroll 1
    for (int oo = 0; oo < 8; oo++) {
        int o = w * 8 + oo;
        float a = fmaf(Wf2[o * 64 + lane],      sf1[lane],      0.0f);
        a       = fmaf(Wf2[o * 64 + lane + 32], sf1[lane + 32], a);
        #pragma unroll
        for (int s = 16; s > 0; s >>= 1) a += __shfl_xor_sync(0xffffffffu, a, s);
        if (lane == 0) sf2[o] = silu_f(a + bf2[o]);
    }
    __syncthreads();

    if (w == 0) {
        float a = fmaf(Wf3[lane],      sf2[lane],      0.0f);
        a       = fmaf(Wf3[lane + 32], sf2[lane + 32], a);
        #pragma unroll
        for (int s = 16; s > 0; s >>= 1) a += __shfl_xor_sync(0xffffffffu, a, s);
        if (lane == 0) out[b] = a + bf3[0] + sred[2];
    }
}

extern "C" void kernel_launch(void* const* d_in, const int* in_sizes, int n_in,
                              void* d_out, int out_size)
{
    const float* x      = (const float*)d_in[0];
    const float* W_node = (const float*)d_in[1];
    const float* b_node = (const float*)d_in[2];
    const float* We1    = (const float*)d_in[3];
    const float* be1    = (const float*)d_in[4];
    const float* We2    = (const float*)d_in[5];
    const float* be2    = (const float*)d_in[6];
    const float* Wv2e   = (const float*)d_in[7];
    const float* We2v   = (const float*)d_in[8];
    const float* Wu1    = (const float*)d_in[9];
    const float* bu1    = (const float*)d_in[10];
    const float* Wu2    = (const float*)d_in[11];
    const float* bu2    = (const float*)d_in[12];
    const float* Wn1    = (const float*)d_in[13];
    const float* bn1    = (const float*)d_in[14];
    const float* Wn2    = (const float*)d_in[15];
    const float* bn2    = (const float*)d_in[16];
    const float* Wf1    = (const float*)d_in[17];
    const float* bf1    = (const float*)d_in[18];
    const float* Wf2    = (const float*)d_in[19];
    const float* bf2    = (const float*)d_in[20];
    const float* Wf3    = (const float*)d_in[21];
    const float* bf3    = (const float*)d_in[22];

    const int dyn_smem = 8 * 2 * 32 * ST * (int)sizeof(float);   // 73728 B
    static bool attr_set = false;
    if (!attr_set) {
        cudaFuncSetAttribute(jastrow_kernel,
                             cudaFuncAttributeMaxDynamicSharedMemorySize, dyn_smem);
        attr_set = true;
    }

    int B = in_sizes[0] / 96;   // (B, 32, 3)
    jastrow_kernel<<<B, 256, dyn_smem>>>(x, W_node, b_node, We1, be1, We2, be2,
                                         Wv2e, We2v, Wu1, bu1, Wu2, bu2,
                                         Wn1, bn1, Wn2, bn2,
                                         Wf1, bf1, Wf2, bf2, Wf3, bf3,
                                         (float*)d_out);
}